// round 1
// baseline (speedup 1.0000x reference)
#include <cuda_runtime.h>
#include <math.h>

#define DD   256
#define BR   64
#define BC   64
#define TPB  256
#define LAMBF 0.002f
#define EPSN  1e-10f
#define EPSS  1e-12f
#define MAXM  4096
#define ST    68   // padded stride for transposed smem tiles

// scratch (allocation-free rule: __device__ globals)
__device__ float g_mnorm[MAXM * DD];
__device__ float g_mlen[MAXM];

// exp(x) via 2^f Taylor-6 + exponent splice. |rel err| < 2e-5 on [-4,4].
// Avoids MUFU.EX2 (0.5/cyc/SM would throttle: 262M exps needed).
__device__ __forceinline__ float fexp(float x) {
    float t  = x * 1.4426950408889634f;
    float fi = floorf(t);
    float f  = t - fi;
    float p  = 1.5403530e-4f;
    p = fmaf(p, f, 1.3333558e-3f);
    p = fmaf(p, f, 9.6181291e-3f);
    p = fmaf(p, f, 5.5504109e-2f);
    p = fmaf(p, f, 2.4022651e-1f);
    p = fmaf(p, f, 6.9314718e-1f);
    p = fmaf(p, f, 1.0f);
    return __int_as_float(__float_as_int(p) + (((int)fi) << 23));
}

// Normalize memory rows -> g_mnorm; keep scale (||m|| + eps) -> g_mlen.
// Pad rows (m >= M) are zeroed so GEMM tiles can run unguarded.
__global__ void mm_norm_mem(const float* __restrict__ mem, int M) {
    int m = blockIdx.x;
    int t = threadIdx.x;
    float v = (m < M) ? mem[(size_t)m * DD + t] : 0.f;
    float ss = v * v;
    #pragma unroll
    for (int o = 16; o; o >>= 1) ss += __shfl_xor_sync(0xffffffffu, ss, o);
    __shared__ float ws[8];
    __shared__ float sc;
    if ((t & 31) == 0) ws[t >> 5] = ss;
    __syncthreads();
    if (t == 0) {
        float tot = 0.f;
        #pragma unroll
        for (int i = 0; i < 8; i++) tot += ws[i];
        sc = sqrtf(tot) + EPSN;
    }
    __syncthreads();
    g_mnorm[(size_t)m * DD + t] = v / sc;
    if (t == 0) g_mlen[m] = (m < M) ? sc : 0.f;
}

// Fused: per CTA = 64 rows of z.
// Phase 1: GEMM1 (z_norm @ m_norm^T), write raw sim into w_hat buffer (scratch,
//          L2-resident), accumulate Z = sum exp(sim)  (no max: |sim| <= 1).
// Phase 2: read sim back, w = exp(s)/Z, hard-shrink -> shr; write shr (unnormalized)
//          back; accumulate S; GEMM2: zacc += shr * ||m|| * m_norm.
// Phase 3: z_hat = zacc/(S+eps); rescale w_hat rows by 1/(S+eps).
__global__ __launch_bounds__(TPB) void mm_fused(
    const float* __restrict__ z,
    float* __restrict__ simbuf,   // = w_hat region of d_out [N, M]
    float* __restrict__ zhat,     // [N, 256]
    int M, int MT)
{
    extern __shared__ float sm[];
    // phase-1 view:
    float* sZt = sm;               // [256][ST]  z_norm transposed (k-major)
    float* sMt = sm + 256 * ST;    // [256][ST]  m_norm tile transposed
    // phase-2 view (overlays phase-1 tiles):
    float* sMn = sm;               // [64][256]  m_norm tile direct
    float* sPt = sm + 16384;       // [64][ST]   shr*||m|| transposed
    // persistent scratch:
    float* red     = sm + 2 * 256 * ST;  // [64][16]
    float* rowInvZ = red + 1024;         // [64]
    float* rowS    = rowInvZ + 64;       // [64]
    float* mlenS   = rowS + 64;          // [64]

    const int tid  = threadIdx.x;
    const int tx   = tid & 15;
    const int ty   = tid >> 4;
    const int lane = tid & 31;
    const long long gr0 = (long long)blockIdx.x * BR;

    // ---- load + normalize z tile into sZt (one row per warp-slot) ----
    {
        int w = tid >> 5;
        #pragma unroll 1
        for (int rr = 0; rr < 8; rr++) {
            int r = w * 8 + rr;
            const float* zr = z + (gr0 + r) * DD;
            float vals[8]; float ss = 0.f;
            #pragma unroll
            for (int q = 0; q < 8; q++) { vals[q] = zr[lane + 32 * q]; ss = fmaf(vals[q], vals[q], ss); }
            #pragma unroll
            for (int o = 16; o; o >>= 1) ss += __shfl_xor_sync(0xffffffffu, ss, o);
            float inv = 1.f / (sqrtf(ss) + EPSN);
            #pragma unroll
            for (int q = 0; q < 8; q++) sZt[(lane + 32 * q) * ST + r] = vals[q] * inv;
        }
    }

    // ================= phase 1 =================
    float Zp[4] = {0.f, 0.f, 0.f, 0.f};
    for (int mt = 0; mt < MT; mt++) {
        const int mbase = mt * BC;
        __syncthreads();
        { // load m_norm tile transposed
            int w = tid >> 5;
            #pragma unroll 1
            for (int rr = 0; rr < 8; rr++) {
                int c = w * 8 + rr;
                const float* mr = g_mnorm + (size_t)(mbase + c) * DD;
                #pragma unroll
                for (int q = 0; q < 8; q++) sMt[(lane + 32 * q) * ST + c] = mr[lane + 32 * q];
            }
        }
        __syncthreads();

        float acc[4][4] = {};
        #pragma unroll 4
        for (int k = 0; k < DD; k++) {
            float4 a4 = *(const float4*)(sZt + k * ST + 4 * ty);
            float4 b4 = *(const float4*)(sMt + k * ST + 4 * tx);
            float av[4] = {a4.x, a4.y, a4.z, a4.w};
            float bv[4] = {b4.x, b4.y, b4.z, b4.w};
            #pragma unroll
            for (int i = 0; i < 4; i++)
                #pragma unroll
                for (int j = 0; j < 4; j++)
                    acc[i][j] = fmaf(av[i], bv[j], acc[i][j]);
        }
        if (mbase + 4 * tx < M) {  // M % 4 == 0: whole float4 valid or skipped
            #pragma unroll
            for (int i = 0; i < 4; i++) {
                int r = 4 * ty + i;
                *(float4*)(simbuf + (gr0 + r) * M + mbase + 4 * tx) =
                    make_float4(acc[i][0], acc[i][1], acc[i][2], acc[i][3]);
                Zp[i] += fexp(acc[i][0]) + fexp(acc[i][1]) + fexp(acc[i][2]) + fexp(acc[i][3]);
            }
        }
    }
    __syncthreads();
    #pragma unroll
    for (int i = 0; i < 4; i++) red[(4 * ty + i) * 16 + tx] = Zp[i];
    __syncthreads();
    if (tid < 64) {
        float s = 0.f;
        #pragma unroll
        for (int j = 0; j < 16; j++) s += red[tid * 16 + j];
        rowInvZ[tid] = 1.0f / s;
        rowS[tid] = 0.f;
    }

    // ================= phase 2 =================
    float zacc[4][4][4] = {};
    for (int mt = 0; mt < MT; mt++) {
        const int mbase = mt * BC;
        __syncthreads();
        // load m_norm tile direct [c][d]
        #pragma unroll 1
        for (int it = 0; it < 16; it++) {
            int r  = it * 4 + (tid >> 6);
            int c4 = (tid & 63) * 4;
            *(float4*)(sMn + r * 256 + c4) =
                *(const float4*)(g_mnorm + (size_t)(mbase + r) * DD + c4);
        }
        if (tid < 64) mlenS[tid] = g_mlen[mbase + tid];
        __syncthreads();

        // shrink + fill sPt + row sums
        #pragma unroll 1
        for (int it = 0; it < 16; it++) {
            int idx = tid + it * 256;
            int r   = idx >> 6;          // warp-uniform
            int c   = idx & 63;
            int col = mbase + c;
            float shr = 0.f;
            if (col < M) {
                float* p = simbuf + (gr0 + r) * M + col;
                float w  = fexp(*p) * rowInvZ[r];
                float d  = w - LAMBF;
                shr = fmaxf(d, 0.f) * w / (fabsf(d) + EPSS);
                *p = shr;                 // unnormalized shr, rescaled in phase 3
            }
            sPt[c * ST + r] = shr * mlenS[c];
            float v = shr;
            #pragma unroll
            for (int o = 16; o; o >>= 1) v += __shfl_xor_sync(0xffffffffu, v, o);
            if (lane == 0) atomicAdd(&rowS[r], v);
        }
        __syncthreads();

        // GEMM2: zacc[r][d] += sPt[c][r] * sMn[c][d]
        #pragma unroll 2
        for (int c = 0; c < BC; c++) {
            float4 a4 = *(const float4*)(sPt + c * ST + 4 * ty);
            float av[4] = {a4.x, a4.y, a4.z, a4.w};
            #pragma unroll
            for (int jb = 0; jb < 4; jb++) {
                float4 b4 = *(const float4*)(sMn + c * 256 + jb * 64 + 4 * tx);
                float bv[4] = {b4.x, b4.y, b4.z, b4.w};
                #pragma unroll
                for (int i = 0; i < 4; i++)
                    #pragma unroll
                    for (int q = 0; q < 4; q++)
                        zacc[i][jb][q] = fmaf(av[i], bv[q], zacc[i][jb][q]);
            }
        }
    }
    __syncthreads();

    // ---- write z_hat ----
    #pragma unroll
    for (int i = 0; i < 4; i++) {
        int r = 4 * ty + i;
        float invS = 1.0f / (rowS[r] + EPSS);
        #pragma unroll
        for (int jb = 0; jb < 4; jb++) {
            float4 o;
            o.x = zacc[i][jb][0] * invS;
            o.y = zacc[i][jb][1] * invS;
            o.z = zacc[i][jb][2] * invS;
            o.w = zacc[i][jb][3] * invS;
            *(float4*)(zhat + (gr0 + r) * DD + jb * 64 + 4 * tx) = o;
        }
    }

    // ================= phase 3: rescale w_hat =================
    #pragma unroll 1
    for (int r = 0; r < BR; r++) {
        float invS = 1.0f / (rowS[r] + EPSS);
        float* wrow = simbuf + (gr0 + r) * M;
        for (int u = tid; 4 * u < M; u += TPB) {
            float4 v = *(float4*)(wrow + 4 * u);
            v.x *= invS; v.y *= invS; v.z *= invS; v.w *= invS;
            *(float4*)(wrow + 4 * u) = v;
        }
    }
}

extern "C" void kernel_launch(void* const* d_in, const int* in_sizes, int n_in,
                              void* d_out, int out_size) {
    const float* z   = (const float*)d_in[0];
    const float* mem = (const float*)d_in[1];
    const int N = in_sizes[0] / DD;
    const int M = in_sizes[1] / DD;
    const int MT = (M + BC - 1) / BC;

    float* zhat   = (float*)d_out;                 // [N, 256] first
    float* simbuf = (float*)d_out + (size_t)N * DD; // [N, M]  second

    static int smem_set = 0;
    const int smem_bytes = (2 * 256 * ST + 1024 + 64 + 64 + 64) * (int)sizeof(float);
    // idempotent; safe to call every launch (not a stream op)
    cudaFuncSetAttribute(mm_fused, cudaFuncAttributeMaxDynamicSharedMemorySize, smem_bytes);
    (void)smem_set;

    mm_norm_mem<<<MT * BC, 256>>>(mem, M);
    mm_fused<<<N / BR, TPB, smem_bytes>>>(z, simbuf, zhat, M, MT);
}

// round 3
// speedup vs baseline: 4.0307x; 4.0307x over previous
#include <cuda_runtime.h>
#include <cuda_bf16.h>
#include <math.h>
#include <stdint.h>

#define DD    256
#define RB    64          // z rows per CTA
#define CH    64          // memory rows per chunk
#define TPB   256
#define LAMBF 0.002f
#define EPSN  1e-10f
#define EPSS  1e-12f
#define MAXM  2048

// pre-swizzled bf16 operand tiles (scratch via __device__ globals)
__device__ __align__(16) __nv_bfloat16 g_mn[MAXM * DD];   // m_norm rows, ldmatrix swizzle
__device__ __align__(16) __nv_bfloat16 g_mt[MAXM * DD];   // mem^T chunk-blocked, ldmatrix swizzle

// ---------------- helpers ----------------
__device__ __forceinline__ uint32_t smem_u32(const void* p) {
    uint32_t a;
    asm("{ .reg .u64 t; cvta.to.shared.u64 t, %1; cvt.u32.u64 %0, t; }" : "=r"(a) : "l"(p));
    return a;
}

#define LDSM4(r0, r1, r2, r3, a) \
    asm volatile("ldmatrix.sync.aligned.m8n8.x4.shared.b16 {%0,%1,%2,%3}, [%4];" \
                 : "=r"(r0), "=r"(r1), "=r"(r2), "=r"(r3) : "r"(a))

#define MMA16816(d, A, b0, b1) \
    asm volatile("mma.sync.aligned.m16n8k16.row.col.f32.bf16.bf16.f32 " \
                 "{%0,%1,%2,%3},{%4,%5,%6,%7},{%8,%9},{%0,%1,%2,%3};" \
                 : "+f"((d)[0]), "+f"((d)[1]), "+f"((d)[2]), "+f"((d)[3]) \
                 : "r"((A)[0]), "r"((A)[1]), "r"((A)[2]), "r"((A)[3]), "r"(b0), "r"(b1))

#define CPASYNC16(dst, src) \
    asm volatile("cp.async.cg.shared.global [%0], [%1], 16;" :: "r"(dst), "l"(src) : "memory")
#define CPCOMMIT() asm volatile("cp.async.commit_group;" ::: "memory")
#define CPWAIT(n)  asm volatile("cp.async.wait_group %0;" :: "n"(n) : "memory")

__device__ __forceinline__ uint32_t bf2(float lo, float hi) {
    uint32_t r;
    asm("cvt.rn.bf16x2.f32 %0, %1, %2;" : "=r"(r) : "f"(hi), "f"(lo));
    return r;
}

// fast exp: 2^f Taylor-6 + exponent splice (avoids MUFU throttle; |rel|<2e-5 on [-4,4])
__device__ __forceinline__ float fexp(float x) {
    float t = x * 1.4426950408889634f;
    float fi = floorf(t);
    float f = t - fi;
    float p = 1.5403530e-4f;
    p = fmaf(p, f, 1.3333558e-3f);
    p = fmaf(p, f, 9.6181291e-3f);
    p = fmaf(p, f, 5.5504109e-2f);
    p = fmaf(p, f, 2.4022651e-1f);
    p = fmaf(p, f, 6.9314718e-1f);
    p = fmaf(p, f, 1.0f);
    return __int_as_float(__float_as_int(p) + (((int)fi) << 23));
}

__device__ __forceinline__ float shrinkf(float w) {
    float d = w - LAMBF;
    return fmaxf(d, 0.f) * w / (fabsf(d) + EPSS);
}

// ---------------- prologue: normalize memory + build swizzled operand tiles ----------------
// g_mn: row m, 512 B/row, 16B-chunk XOR swizzle: elem = m*256 + ((d>>3)^(m&7))*8 + (d&7)
// g_mt: chunk ch=m>>6, 256 d-rows x 64 cols, 128 B/row:
//       elem = ch*16384 + d*64 + (((c>>3)^(d&7))*8) + (c&7),  c = m&63
__global__ void mm_prep(const float* __restrict__ mem, int M) {
    int m = blockIdx.x;
    int d = threadIdx.x;
    float v = (m < M) ? mem[(size_t)m * DD + d] : 0.f;
    float ss = v * v;
    #pragma unroll
    for (int o = 16; o; o >>= 1) ss += __shfl_xor_sync(0xffffffffu, ss, o);
    __shared__ float ws[8];
    __shared__ float sc;
    if ((d & 31) == 0) ws[d >> 5] = ss;
    __syncthreads();
    if (d == 0) {
        float t = 0.f;
        #pragma unroll
        for (int i = 0; i < 8; i++) t += ws[i];
        sc = sqrtf(t) + EPSN;
    }
    __syncthreads();
    g_mn[m * 256 + (((d >> 3) ^ (m & 7)) * 8) + (d & 7)] = __float2bfloat16(v / sc);
    int ch = m >> 6, c = m & 63;
    g_mt[ch * 16384 + d * 64 + (((c >> 3) ^ (d & 7)) * 8) + (c & 7)] = __float2bfloat16(v);
}

// ---------------- GEMM micro-kernels ----------------
// GEMM1: sim chunk C[64 x 64] = A_z[64 x 256] @ B[64 x 256]^T, warp tile 16x32
__device__ __forceinline__ void gemm1(uint32_t sA, uint32_t sB, int wr, int wc, int lane,
                                      float acc[16]) {
    const uint32_t h = lane >> 4;
    const uint32_t arow = wr * 16 + (lane & 15);
    const uint32_t abase = sA + arow * 512;
    const uint32_t arx = arow & 7;
    const uint32_t brow = wc * 32 + (lane & 15);
    const uint32_t bbase = sB + brow * 512;
    const uint32_t brx = brow & 7;
    #pragma unroll
    for (int kk = 0; kk < 16; kk++) {
        uint32_t ca = ((uint32_t)(kk * 2 + h) ^ arx) << 4;
        uint32_t cb = ((uint32_t)(kk * 2 + h) ^ brx) << 4;
        uint32_t A[4], p0, p1, p2, p3, q0, q1, q2, q3;
        LDSM4(A[0], A[1], A[2], A[3], abase + ca);
        LDSM4(p0, p1, p2, p3, bbase + cb);
        LDSM4(q0, q1, q2, q3, bbase + 16 * 512 + cb);
        MMA16816(acc + 0,  A, p0, p2);
        MMA16816(acc + 4,  A, p1, p3);
        MMA16816(acc + 8,  A, q0, q2);
        MMA16816(acc + 12, A, q1, q3);
    }
}

// GEMM2: zhat[64 x 256] += P[64 x 64] @ mem[64 x 256]; B = memT[256 d x 64 k]
__device__ __forceinline__ void gemm2(uint32_t sP, uint32_t sB2, int wr, int wc, int lane,
                                      float zac[64]) {
    const uint32_t h = lane >> 4;
    const uint32_t prow = wr * 16 + (lane & 15);
    const uint32_t pbase = sP + prow * 128;
    const uint32_t prx = prow & 7;
    const uint32_t drow = wc * 128 + (lane & 15);
    const uint32_t dbase = sB2 + drow * 128;
    const uint32_t drx = drow & 7;
    #pragma unroll
    for (int kk = 0; kk < 4; kk++) {
        uint32_t ca = ((uint32_t)(kk * 2 + h) ^ prx) << 4;
        uint32_t cb = ((uint32_t)(kk * 2 + h) ^ drx) << 4;
        uint32_t A[4];
        LDSM4(A[0], A[1], A[2], A[3], pbase + ca);
        #pragma unroll
        for (int g = 0; g < 8; g++) {
            uint32_t b0, b1, b2, b3;
            LDSM4(b0, b1, b2, b3, dbase + g * 2048 + cb);
            MMA16816(zac + (g * 2) * 4,     A, b0, b2);
            MMA16816(zac + (g * 2 + 1) * 4, A, b1, b3);
        }
    }
}

// async 32 KB chunk copy (global pre-swizzled -> smem linear)
__device__ __forceinline__ void copyB(uint32_t sdst, const __nv_bfloat16* g) {
    const char* gp = (const char*)g;
    #pragma unroll
    for (int k = 0; k < 8; k++) {
        int idx = threadIdx.x + k * 256;
        CPASYNC16(sdst + idx * 16, gp + (size_t)idx * 16);
    }
}

// smem offsets (bytes)
#define A_OFF   0
#define B1_OFF  32768
#define B2_OFF  65536
#define WB_OFF  65536      // pass-3 staging aliases B2
#define P_OFF   98304
#define RED_OFF 106496
#define ZS_OFF  108544
#define SS_OFF  108800
#define SM_TOT  109056

__global__ __launch_bounds__(TPB, 2) void mm_main(
    const float* __restrict__ z,
    float* __restrict__ wout,     // [N, M]
    float* __restrict__ zhat,     // [N, 256]
    int M, int NCH)
{
    extern __shared__ char smc[];
    const uint32_t sbase = smem_u32(smc);
    const uint32_t sA = sbase + A_OFF, sB1 = sbase + B1_OFF, sB2 = sbase + B2_OFF;
    const uint32_t sP = sbase + P_OFF;
    float* red = (float*)(smc + RED_OFF);
    float* Zs  = (float*)(smc + ZS_OFF);
    float* Ss  = (float*)(smc + SS_OFF);

    const int tid = threadIdx.x, wid = tid >> 5, lane = tid & 31;
    const int wr = wid >> 1, wc = wid & 1;
    const long long gr0 = (long long)blockIdx.x * RB;
    const int r0l = wr * 16 + (lane >> 2), r1l = r0l + 8;

    // ---- build A tile: normalize z rows, bf16, swizzled ----
    #pragma unroll 1
    for (int i = 0; i < 8; i++) {
        int r = wid * 8 + i;
        const float4* zr = (const float4*)(z + (gr0 + r) * DD);
        float4 a = zr[lane * 2], b = zr[lane * 2 + 1];
        float ss = a.x*a.x + a.y*a.y + a.z*a.z + a.w*a.w
                 + b.x*b.x + b.y*b.y + b.z*b.z + b.w*b.w;
        #pragma unroll
        for (int o = 16; o; o >>= 1) ss += __shfl_xor_sync(0xffffffffu, ss, o);
        float inv = 1.f / (sqrtf(ss) + EPSN);
        uint4 u;
        u.x = bf2(a.x * inv, a.y * inv); u.y = bf2(a.z * inv, a.w * inv);
        u.z = bf2(b.x * inv, b.y * inv); u.w = bf2(b.z * inv, b.w * inv);
        *(uint4*)(smc + A_OFF + r * 512 + ((lane ^ (r & 7)) * 16)) = u;
    }
    __syncthreads();

    // ================= PASS 1: Z =================
    float z0 = 0.f, z1 = 0.f;
    for (int ch = 0; ch < NCH; ch++) {
        __syncthreads();
        copyB(sB1, g_mn + (size_t)ch * CH * DD);
        CPCOMMIT(); CPWAIT(0);
        __syncthreads();
        float acc[16] = {};
        gemm1(sA, sB1, wr, wc, lane, acc);
        #pragma unroll
        for (int nt = 0; nt < 4; nt++) {
            int col = ch * CH + wc * 32 + nt * 8 + 2 * (lane & 3);
            if (col < M) {
                z0 += fexp(acc[nt * 4 + 0]) + fexp(acc[nt * 4 + 1]);
                z1 += fexp(acc[nt * 4 + 2]) + fexp(acc[nt * 4 + 3]);
            }
        }
    }
    __syncthreads();
    red[r0l * 8 + wc * 4 + (lane & 3)] = z0;
    red[r1l * 8 + wc * 4 + (lane & 3)] = z1;
    __syncthreads();
    if (tid < 64) {
        float s = 0.f;
        #pragma unroll
        for (int j = 0; j < 8; j++) s += red[tid * 8 + j];
        Zs[tid] = 1.0f / s;
    }
    __syncthreads();
    const float invZ0 = Zs[r0l], invZ1 = Zs[r1l];

    // ================= PASS 2: S + z_hat accumulation =================
    float s0 = 0.f, s1 = 0.f;
    float zac[64] = {};
    for (int ch = 0; ch < NCH; ch++) {
        __syncthreads();
        copyB(sB1, g_mn + (size_t)ch * CH * DD); CPCOMMIT();
        copyB(sB2, g_mt + (size_t)ch * CH * DD); CPCOMMIT();
        CPWAIT(1);
        __syncthreads();
        float acc[16] = {};
        gemm1(sA, sB1, wr, wc, lane, acc);
        #pragma unroll
        for (int nt = 0; nt < 4; nt++) {
            int cl  = wc * 32 + nt * 8 + 2 * (lane & 3);
            int col = ch * CH + cl;
            float h00 = 0.f, h01 = 0.f, h10 = 0.f, h11 = 0.f;
            if (col < M) {
                h00 = shrinkf(fexp(acc[nt * 4 + 0]) * invZ0);
                h01 = shrinkf(fexp(acc[nt * 4 + 1]) * invZ0);
                h10 = shrinkf(fexp(acc[nt * 4 + 2]) * invZ1);
                h11 = shrinkf(fexp(acc[nt * 4 + 3]) * invZ1);
            }
            s0 += h00 + h01; s1 += h10 + h11;
            uint32_t sw0 = (uint32_t)(((cl >> 3) ^ (r0l & 7)) * 16 + (cl & 7) * 2);
            uint32_t sw1 = (uint32_t)(((cl >> 3) ^ (r1l & 7)) * 16 + (cl & 7) * 2);
            *(uint32_t*)(smc + P_OFF + r0l * 128 + sw0) = bf2(h00, h01);
            *(uint32_t*)(smc + P_OFF + r1l * 128 + sw1) = bf2(h10, h11);
        }
        CPWAIT(0);
        __syncthreads();
        gemm2(sP, sB2, wr, wc, lane, zac);
    }
    __syncthreads();
    red[r0l * 8 + wc * 4 + (lane & 3)] = s0;
    red[r1l * 8 + wc * 4 + (lane & 3)] = s1;
    __syncthreads();
    if (tid < 64) {
        float s = 0.f;
        #pragma unroll
        for (int j = 0; j < 8; j++) s += red[tid * 8 + j];
        Ss[tid] = 1.0f / (s + EPSS);
    }
    __syncthreads();
    const float invS0 = Ss[r0l], invS1 = Ss[r1l];

    // ---- write z_hat ----
    {
        float* zr0 = zhat + (gr0 + r0l) * DD;
        float* zr1 = zhat + (gr0 + r1l) * DD;
        #pragma unroll
        for (int g = 0; g < 8; g++) {
            #pragma unroll
            for (int t = 0; t < 2; t++) {
                int d = wc * 128 + g * 16 + t * 8 + 2 * (lane & 3);
                int ii = (g * 2 + t) * 4;
                *(float2*)(zr0 + d) = make_float2(zac[ii + 0] * invS0, zac[ii + 1] * invS0);
                *(float2*)(zr1 + d) = make_float2(zac[ii + 2] * invS1, zac[ii + 3] * invS1);
            }
        }
    }

    // ================= PASS 3: w_hat =================
    for (int ch = 0; ch < NCH; ch++) {
        __syncthreads();
        copyB(sB1, g_mn + (size_t)ch * CH * DD);
        CPCOMMIT(); CPWAIT(0);
        __syncthreads();
        float acc[16] = {};
        gemm1(sA, sB1, wr, wc, lane, acc);
        #pragma unroll
        for (int nt = 0; nt < 4; nt++) {
            int cl = wc * 32 + nt * 8 + 2 * (lane & 3);
            float w00 = shrinkf(fexp(acc[nt * 4 + 0]) * invZ0) * invS0;
            float w01 = shrinkf(fexp(acc[nt * 4 + 1]) * invZ0) * invS0;
            float w10 = shrinkf(fexp(acc[nt * 4 + 2]) * invZ1) * invS1;
            float w11 = shrinkf(fexp(acc[nt * 4 + 3]) * invZ1) * invS1;
            uint32_t sw0 = (uint32_t)(((cl >> 2) ^ (r0l & 7)) * 16 + (cl & 3) * 4);
            uint32_t sw1 = (uint32_t)(((cl >> 2) ^ (r1l & 7)) * 16 + (cl & 3) * 4);
            *(float2*)(smc + WB_OFF + r0l * 256 + sw0) = make_float2(w00, w01);
            *(float2*)(smc + WB_OFF + r1l * 256 + sw1) = make_float2(w10, w11);
        }
        __syncthreads();
        #pragma unroll
        for (int k = 0; k < 4; k++) {
            int idx = tid + k * 256;
            int r = idx >> 4, j = idx & 15;
            int col = ch * CH + j * 4;
            if (col < M) {
                float4 v = *(float4*)(smc + WB_OFF + r * 256 + ((j ^ (r & 7)) * 16));
                *(float4*)(wout + (gr0 + r) * (long long)M + col) = v;
            }
        }
    }
}

// ---------------- host ----------------
extern "C" void kernel_launch(void* const* d_in, const int* in_sizes, int n_in,
                              void* d_out, int out_size) {
    const float* z   = (const float*)d_in[0];
    const float* mem = (const float*)d_in[1];
    const int N = in_sizes[0] / DD;
    const int M = in_sizes[1] / DD;
    const int NCH = (M + CH - 1) / CH;

    float* zhat = (float*)d_out;                 // [N, 256]
    float* wout = zhat + (size_t)N * DD;         // [N, M]

    cudaFuncSetAttribute(mm_main, cudaFuncAttributeMaxDynamicSharedMemorySize, SM_TOT);

    mm_prep<<<NCH * CH, 256>>>(mem, M);
    mm_main<<<N / RB, TPB, SM_TOT>>>(z, wout, zhat, M, NCH);
}

// round 5
// speedup vs baseline: 11.6740x; 2.8963x over previous
#include <cuda_runtime.h>
#include <cuda_bf16.h>
#include <math.h>
#include <stdint.h>

#define DD    256
#define RB    64          // z rows per CTA
#define CH    64          // memory cols per chunk
#define TPB   256
#define LAMBF 0.002f
#define EPSN  1e-10f
#define EPSS  1e-12f
#define MAXM  2048

// pre-swizzled bf16 operand tiles (scratch via __device__ globals)
__device__ __align__(16) __nv_bfloat16 g_mn[MAXM * DD];   // m_norm rows, ldmatrix swizzle
__device__ __align__(16) __nv_bfloat16 g_mt[MAXM * DD];   // mem^T chunk-blocked, ldmatrix swizzle

// ---------------- helpers ----------------
__device__ __forceinline__ uint32_t smem_u32(const void* p) {
    uint32_t a;
    asm("{ .reg .u64 t; cvta.to.shared.u64 t, %1; cvt.u32.u64 %0, t; }" : "=r"(a) : "l"(p));
    return a;
}

#define LDSM4(r0, r1, r2, r3, a) \
    asm volatile("ldmatrix.sync.aligned.m8n8.x4.shared.b16 {%0,%1,%2,%3}, [%4];" \
                 : "=r"(r0), "=r"(r1), "=r"(r2), "=r"(r3) : "r"(a))

#define MMA16816(d, A, b0, b1) \
    asm volatile("mma.sync.aligned.m16n8k16.row.col.f32.bf16.bf16.f32 " \
                 "{%0,%1,%2,%3},{%4,%5,%6,%7},{%8,%9},{%0,%1,%2,%3};" \
                 : "+f"((d)[0]), "+f"((d)[1]), "+f"((d)[2]), "+f"((d)[3]) \
                 : "r"((A)[0]), "r"((A)[1]), "r"((A)[2]), "r"((A)[3]), "r"(b0), "r"(b1))

#define CPASYNC16(dst, src) \
    asm volatile("cp.async.cg.shared.global [%0], [%1], 16;" :: "r"(dst), "l"(src) : "memory")
#define CPCOMMIT() asm volatile("cp.async.commit_group;" ::: "memory")
#define CPWAIT(n)  asm volatile("cp.async.wait_group %0;" :: "n"(n) : "memory")

__device__ __forceinline__ uint32_t bf2(float lo, float hi) {
    uint32_t r;
    asm("cvt.rn.bf16x2.f32 %0, %1, %2;" : "=r"(r) : "f"(hi), "f"(lo));
    return r;
}
__device__ __forceinline__ float bflo(uint32_t u) { return __uint_as_float(u << 16); }
__device__ __forceinline__ float bfhi(uint32_t u) { return __uint_as_float(u & 0xffff0000u); }

// fast exp: 2^f Taylor-6 + exponent splice (|rel|<2e-5 on [-4,4])
__device__ __forceinline__ float fexp(float x) {
    float t = x * 1.4426950408889634f;
    float fi = floorf(t);
    float f = t - fi;
    float p = 1.5403530e-4f;
    p = fmaf(p, f, 1.3333558e-3f);
    p = fmaf(p, f, 9.6181291e-3f);
    p = fmaf(p, f, 5.5504109e-2f);
    p = fmaf(p, f, 2.4022651e-1f);
    p = fmaf(p, f, 6.9314718e-1f);
    p = fmaf(p, f, 1.0f);
    return __int_as_float(__float_as_int(p) + (((int)fi) << 23));
}

__device__ __forceinline__ float shrinkf(float w) {
    float d = w - LAMBF;
    return fmaxf(d, 0.f) * w / (fabsf(d) + EPSS);
}

// ---------------- prologue: normalize memory + build swizzled operand tiles ----------------
__global__ void mm_prep(const float* __restrict__ mem, int M) {
    int m = blockIdx.x;
    int d = threadIdx.x;
    float v = (m < M) ? mem[(size_t)m * DD + d] : 0.f;
    float ss = v * v;
    #pragma unroll
    for (int o = 16; o; o >>= 1) ss += __shfl_xor_sync(0xffffffffu, ss, o);
    __shared__ float ws[8];
    __shared__ float sc;
    if ((d & 31) == 0) ws[d >> 5] = ss;
    __syncthreads();
    if (d == 0) {
        float t = 0.f;
        #pragma unroll
        for (int i = 0; i < 8; i++) t += ws[i];
        sc = sqrtf(t) + EPSN;
    }
    __syncthreads();
    g_mn[m * 256 + (((d >> 3) ^ (m & 7)) * 8) + (d & 7)] = __float2bfloat16(v / sc);
    int ch = m >> 6, c = m & 63;
    g_mt[ch * 16384 + d * 64 + (((c >> 3) ^ (d & 7)) * 8) + (c & 7)] = __float2bfloat16(v);
}

// ---------------- GEMM micro-kernels ----------------
__device__ __forceinline__ void gemm1(uint32_t sA, uint32_t sB, int wr, int wc, int lane,
                                      float acc[16]) {
    const uint32_t h = lane >> 4;
    const uint32_t arow = wr * 16 + (lane & 15);
    const uint32_t abase = sA + arow * 512;
    const uint32_t arx = arow & 7;
    const uint32_t brow = wc * 32 + (lane & 15);
    const uint32_t bbase = sB + brow * 512;
    const uint32_t brx = brow & 7;
    #pragma unroll
    for (int kk = 0; kk < 16; kk++) {
        uint32_t ca = ((uint32_t)(kk * 2 + h) ^ arx) << 4;
        uint32_t cb = ((uint32_t)(kk * 2 + h) ^ brx) << 4;
        uint32_t A[4], p0, p1, p2, p3, q0, q1, q2, q3;
        LDSM4(A[0], A[1], A[2], A[3], abase + ca);
        LDSM4(p0, p1, p2, p3, bbase + cb);
        LDSM4(q0, q1, q2, q3, bbase + 16 * 512 + cb);
        MMA16816(acc + 0,  A, p0, p2);
        MMA16816(acc + 4,  A, p1, p3);
        MMA16816(acc + 8,  A, q0, q2);
        MMA16816(acc + 12, A, q1, q3);
    }
}

__device__ __forceinline__ void gemm2(uint32_t sP, uint32_t sB2, int wr, int wc, int lane,
                                      float zac[64]) {
    const uint32_t h = lane >> 4;
    const uint32_t prow = wr * 16 + (lane & 15);
    const uint32_t pbase = sP + prow * 128;
    const uint32_t prx = prow & 7;
    const uint32_t drow = wc * 128 + (lane & 15);
    const uint32_t dbase = sB2 + drow * 128;
    const uint32_t drx = drow & 7;
    #pragma unroll
    for (int kk = 0; kk < 4; kk++) {
        uint32_t ca = ((uint32_t)(kk * 2 + h) ^ prx) << 4;
        uint32_t cb = ((uint32_t)(kk * 2 + h) ^ drx) << 4;
        uint32_t A[4];
        LDSM4(A[0], A[1], A[2], A[3], pbase + ca);
        #pragma unroll
        for (int g = 0; g < 8; g++) {
            uint32_t b0, b1, b2, b3;
            LDSM4(b0, b1, b2, b3, dbase + g * 2048 + cb);
            MMA16816(zac + (g * 2) * 4,     A, b0, b2);
            MMA16816(zac + (g * 2 + 1) * 4, A, b1, b3);
        }
    }
}

__device__ __forceinline__ void copyB(uint32_t sdst, const __nv_bfloat16* g) {
    const char* gp = (const char*)g;
    #pragma unroll
    for (int k = 0; k < 8; k++) {
        int idx = threadIdx.x + k * 256;
        CPASYNC16(sdst + idx * 16, gp + (size_t)idx * 16);
    }
}

// smem offsets (bytes)
#define A_OFF   0          // pass1 A tile (32K) | pass2 sweep buffers
#define B1A_OFF 32768      // pass1 B dbl
#define B1B_OFF 65536
#define SIMST   98304      // pass1 sim staging (8K) | w-sweep P (8K)
#define P_OFF   98304
#define SB0_OFF 0          // S-sweep dbl (16K each)
#define SB1_OFF 16384
#define SIMA    0          // w-sweep sim dbl (8K each)
#define SIMB    8192
#define WB_OFF  16384      // w-sweep staging (16K)
#define MT_OFF  32768      // w-sweep memT tile (32K)
#define RED_OFF 106496     // 512 floats (2K) — Z reduction needs 64 rows x 8 partials
#define ZS_OFF  108544     // invZ[64]
#define TS_OFF  108800     // thresholds[64]
#define SS_OFF  109056     // invS[64]
#define SM_TOT  109312

__global__ __launch_bounds__(TPB, 2) void mm_main(
    const float* __restrict__ z,
    float* __restrict__ wout,     // [N, M]
    float* __restrict__ zhat,     // [N, 256]
    int M, int NCH)
{
    extern __shared__ char smc[];
    const uint32_t sbase = smem_u32(smc);
    const uint32_t sA = sbase + A_OFF;
    float* red = (float*)(smc + RED_OFF);
    int*   flg = (int*)(smc + RED_OFF);     // reused in w-sweep
    float* Zs  = (float*)(smc + ZS_OFF);
    float* Ts  = (float*)(smc + TS_OFF);
    float* Ss  = (float*)(smc + SS_OFF);

    const int tid = threadIdx.x, wid = tid >> 5, lane = tid & 31;
    const int wr = wid >> 1, wc = wid & 1;
    const long long gr0 = (long long)blockIdx.x * RB;
    const int r0l = wr * 16 + (lane >> 2), r1l = r0l + 8;

    char* slice = (char*)(wout + gr0 * (long long)M);
    const int RSTR = 4 * M;        // bytes per w_hat row in slice
    const int SOFF = 2 * M;        // sim region offset within a row (== sim region size)

    // ---- build A tile: normalize z rows, bf16, swizzled ----
    #pragma unroll 1
    for (int i = 0; i < 8; i++) {
        int r = wid * 8 + i;
        const float4* zr = (const float4*)(z + (gr0 + r) * DD);
        float4 a = zr[lane * 2], b = zr[lane * 2 + 1];
        float ss = a.x*a.x + a.y*a.y + a.z*a.z + a.w*a.w
                 + b.x*b.x + b.y*b.y + b.z*b.z + b.w*b.w;
        #pragma unroll
        for (int o = 16; o; o >>= 1) ss += __shfl_xor_sync(0xffffffffu, ss, o);
        float inv = 1.f / (sqrtf(ss) + EPSN);
        uint4 u;
        u.x = bf2(a.x * inv, a.y * inv); u.y = bf2(a.z * inv, a.w * inv);
        u.z = bf2(b.x * inv, b.y * inv); u.w = bf2(b.z * inv, b.w * inv);
        *(uint4*)(smc + A_OFF + r * 512 + ((lane ^ (r & 7)) * 16)) = u;
    }
    __syncthreads();

    // ================= PASS 1: GEMM1 once; Z; store sim bf16 =================
    float z0 = 0.f, z1 = 0.f;
    copyB(sbase + B1A_OFF, g_mn); CPCOMMIT();
    for (int ch = 0; ch < NCH; ch++) {
        __syncthreads();
        if (ch + 1 < NCH) copyB(sbase + (((ch + 1) & 1) ? B1B_OFF : B1A_OFF),
                                g_mn + (size_t)(ch + 1) * CH * DD);
        CPCOMMIT(); CPWAIT(1);
        __syncthreads();
        float acc[16] = {};
        gemm1(sA, sbase + ((ch & 1) ? B1B_OFF : B1A_OFF), wr, wc, lane, acc);
        #pragma unroll
        for (int nt = 0; nt < 4; nt++) {
            int cl  = wc * 32 + nt * 8 + 2 * (lane & 3);
            int col = ch * CH + cl;
            *(uint32_t*)(smc + SIMST + r0l * 128 + (((cl >> 3) ^ (r0l & 7)) << 4) + (cl & 7) * 2)
                = bf2(acc[nt * 4 + 0], acc[nt * 4 + 1]);
            *(uint32_t*)(smc + SIMST + r1l * 128 + (((cl >> 3) ^ (r1l & 7)) << 4) + (cl & 7) * 2)
                = bf2(acc[nt * 4 + 2], acc[nt * 4 + 3]);
            if (col < M) {
                z0 += fexp(acc[nt * 4 + 0]) + fexp(acc[nt * 4 + 1]);
                z1 += fexp(acc[nt * 4 + 2]) + fexp(acc[nt * 4 + 3]);
            }
        }
        __syncthreads();
        #pragma unroll
        for (int k = 0; k < 2; k++) {
            int idx = tid + k * 256;
            int r = idx >> 3, g = idx & 7;
            if (ch * CH + g * 8 < M)
                *(uint4*)(slice + (size_t)r * RSTR + SOFF + ch * 128 + g * 16) =
                    *(uint4*)(smc + SIMST + r * 128 + ((g ^ (r & 7)) << 4));
        }
    }
    __threadfence();
    __syncthreads();
    // Z reduction: 8 disjoint partial slots per row (2 wc x 4 quad-lanes)
    red[r0l * 8 + wc * 4 + (lane & 3)] = z0;
    red[r1l * 8 + wc * 4 + (lane & 3)] = z1;
    __syncthreads();
    if (tid < 64) {
        float s = 0.f;
        #pragma unroll
        for (int j = 0; j < 8; j++) s += red[tid * 8 + j];
        Zs[tid] = 1.0f / s;
        Ts[tid] = logf(LAMBF * s) - 1e-3f;   // conservative skip threshold
    }
    __syncthreads();

    // ================= PASS 2a: S-sweep (threshold fast path) =================
    const int rS  = tid >> 2;
    const float invZr = Zs[rS], Tr = Ts[rS];
    const int NS = (M + 127) / 128;
    float sacc = 0.f;
    {
        #pragma unroll
        for (int k = 0; k < 4; k++) {
            int idx = tid + k * 256;
            int r = idx >> 4, seg = idx & 15;
            if (seg * 16 < SOFF)
                CPASYNC16(sbase + SB0_OFF + idx * 16,
                          slice + (size_t)r * RSTR + SOFF + seg * 16);
        }
        CPCOMMIT();
    }
    for (int s = 0; s < NS; s++) {
        if (s + 1 < NS) {
            #pragma unroll
            for (int k = 0; k < 4; k++) {
                int idx = tid + k * 256;
                int r = idx >> 4, seg = idx & 15;
                int off = (s + 1) * 256 + seg * 16;
                if (off < SOFF)
                    CPASYNC16(sbase + (((s + 1) & 1) ? SB1_OFF : SB0_OFF) + idx * 16,
                              slice + (size_t)r * RSTR + SOFF + off);
            }
        }
        CPCOMMIT(); CPWAIT(1);
        __syncthreads();
        const uint32_t sb = sbase + ((s & 1) ? SB1_OFF : SB0_OFF) + rS * 256 + (tid & 3) * 64;
        uint32_t v[16];
        #pragma unroll
        for (int q = 0; q < 4; q++) {
            uint4 u; asm volatile("ld.shared.v4.u32 {%0,%1,%2,%3}, [%4];"
                : "=r"(u.x), "=r"(u.y), "=r"(u.z), "=r"(u.w) : "r"(sb + q * 16));
            v[q*4]=u.x; v[q*4+1]=u.y; v[q*4+2]=u.z; v[q*4+3]=u.w;
        }
        #pragma unroll
        for (int j = 0; j < 16; j++) {
            int col = s * 128 + (tid & 3) * 32 + 2 * j;
            float lo = bflo(v[j]), hi = bfhi(v[j]);
            if (col < M && lo > Tr)     sacc += shrinkf(fexp(lo) * invZr);
            if (col + 1 < M && hi > Tr) sacc += shrinkf(fexp(hi) * invZr);
        }
        __syncthreads();
    }
    red[tid] = sacc;
    __syncthreads();
    if (tid < 64)
        Ss[tid] = 1.0f / (red[4 * tid] + red[4 * tid + 1] + red[4 * tid + 2] + red[4 * tid + 3] + EPSS);
    __syncthreads();

    // ================= PASS 2b: w-sweep (w_hat + sparse GEMM2) =================
    const float invSr = Ss[rS];
    float zac[64] = {};
    {
        #pragma unroll
        for (int k = 0; k < 2; k++) {
            int idx = tid + k * 256;
            int r = idx >> 3, g = idx & 7;
            if (g * 16 < SOFF)
                CPASYNC16(sbase + SIMA + idx * 16, slice + (size_t)r * RSTR + SOFF + g * 16);
        }
        CPCOMMIT();
    }
    for (int ch = 0; ch < NCH; ch++) {
        __syncthreads();
        if (tid == 0) *flg = 0;
        if (ch + 1 < NCH) {
            #pragma unroll
            for (int k = 0; k < 2; k++) {
                int idx = tid + k * 256;
                int r = idx >> 3, g = idx & 7;
                int off = (ch + 1) * 128 + g * 16;
                if (off < SOFF)
                    CPASYNC16(sbase + (((ch + 1) & 1) ? SIMB : SIMA) + idx * 16,
                              slice + (size_t)r * RSTR + SOFF + off);
            }
        }
        CPCOMMIT(); CPWAIT(1);
        __syncthreads();
        {
            const uint32_t sb = sbase + ((ch & 1) ? SIMB : SIMA) + rS * 128 + (tid & 3) * 32;
            uint32_t v[8];
            #pragma unroll
            for (int q = 0; q < 2; q++) {
                uint4 u; asm volatile("ld.shared.v4.u32 {%0,%1,%2,%3}, [%4];"
                    : "=r"(u.x), "=r"(u.y), "=r"(u.z), "=r"(u.w) : "r"(sb + q * 16));
                v[q*4]=u.x; v[q*4+1]=u.y; v[q*4+2]=u.z; v[q*4+3]=u.w;
            }
            int rare = 0;
            #pragma unroll
            for (int j = 0; j < 8; j++) {
                int cl  = (tid & 3) * 16 + 2 * j;
                int col = ch * CH + cl;
                float lo = bflo(v[j]), hi = bfhi(v[j]);
                float h0 = 0.f, h1 = 0.f;
                if (col < M && lo > Tr)     h0 = shrinkf(fexp(lo) * invZr);
                if (col + 1 < M && hi > Tr) h1 = shrinkf(fexp(hi) * invZr);
                rare |= (h0 > 0.f) | (h1 > 0.f);
                *(uint32_t*)(smc + P_OFF + rS * 128 + (((cl >> 3) ^ (rS & 7)) << 4) + (cl & 7) * 2)
                    = bf2(h0, h1);
                *(float2*)(smc + WB_OFF + rS * 256 + (((cl >> 2) ^ (rS & 7)) << 4) + (cl & 3) * 4)
                    = make_float2(h0 * invSr, h1 * invSr);
            }
            if (rare) *flg = 1;
        }
        __syncthreads();
        if (*flg) {   // uniform branch: rare path, run GEMM2 for this chunk
            copyB(sbase + MT_OFF, g_mt + (size_t)ch * CH * DD);
            CPCOMMIT(); CPWAIT(0);
            __syncthreads();
            gemm2(sbase + P_OFF, sbase + MT_OFF, wr, wc, lane, zac);
            __syncthreads();
        }
        #pragma unroll
        for (int k = 0; k < 4; k++) {
            int idx = tid + k * 256;
            int r = idx >> 4, j = idx & 15;
            int col = ch * CH + j * 4;
            if (col < M)
                *(uint4*)(wout + (gr0 + r) * (long long)M + col) =
                    *(uint4*)(smc + WB_OFF + r * 256 + ((j ^ (r & 7)) << 4));
        }
    }

    // ---- z_hat epilogue ----
    {
        const float invS0 = Ss[r0l], invS1 = Ss[r1l];
        float* zr0 = zhat + (gr0 + r0l) * DD;
        float* zr1 = zhat + (gr0 + r1l) * DD;
        #pragma unroll
        for (int g = 0; g < 8; g++) {
            #pragma unroll
            for (int t = 0; t < 2; t++) {
                int d = wc * 128 + g * 16 + t * 8 + 2 * (lane & 3);
                int ii = (g * 2 + t) * 4;
                *(float2*)(zr0 + d) = make_float2(zac[ii + 0] * invS0, zac[ii + 1] * invS0);
                *(float2*)(zr1 + d) = make_float2(zac[ii + 2] * invS1, zac[ii + 3] * invS1);
            }
        }
    }
}

// ---------------- host ----------------
extern "C" void kernel_launch(void* const* d_in, const int* in_sizes, int n_in,
                              void* d_out, int out_size) {
    const float* z   = (const float*)d_in[0];
    const float* mem = (const float*)d_in[1];
    const int N = in_sizes[0] / DD;
    const int M = in_sizes[1] / DD;
    const int NCH = (M + CH - 1) / CH;

    float* zhat = (float*)d_out;                 // [N, 256]
    float* wout = zhat + (size_t)N * DD;         // [N, M]

    cudaFuncSetAttribute(mm_main, cudaFuncAttributeMaxDynamicSharedMemorySize, SM_TOT);

    mm_prep<<<NCH * CH, 256>>>(mem, M);
    mm_main<<<N / RB, TPB, SM_TOT>>>(z, wout, zhat, M, NCH);
}

// round 6
// speedup vs baseline: 14.8025x; 1.2680x over previous
#include <cuda_runtime.h>
#include <cuda_bf16.h>
#include <math.h>
#include <stdint.h>

#define DD    256
#define RB    64          // z rows per CTA
#define CH    64          // memory cols per chunk
#define TPB   256
#define LAMBF 0.002f
#define EPSN  1e-10f
#define EPSS  1e-12f
#define MAXM  2048
#define LCAP  8192        // sparse fixup list capacity (per CTA)

// pre-swizzled bf16 operand tiles (scratch via __device__ globals)
__device__ __align__(16) __nv_bfloat16 g_mn[MAXM * DD];   // m_norm rows, ldmatrix swizzle
__device__ __align__(16) __nv_bfloat16 g_mt[MAXM * DD];   // mem^T chunk-blocked, ldmatrix swizzle

// ---------------- helpers ----------------
__device__ __forceinline__ uint32_t smem_u32(const void* p) {
    uint32_t a;
    asm("{ .reg .u64 t; cvta.to.shared.u64 t, %1; cvt.u32.u64 %0, t; }" : "=r"(a) : "l"(p));
    return a;
}

#define LDSM4(r0, r1, r2, r3, a) \
    asm volatile("ldmatrix.sync.aligned.m8n8.x4.shared.b16 {%0,%1,%2,%3}, [%4];" \
                 : "=r"(r0), "=r"(r1), "=r"(r2), "=r"(r3) : "r"(a))

#define MMA16816(d, A, b0, b1) \
    asm volatile("mma.sync.aligned.m16n8k16.row.col.f32.bf16.bf16.f32 " \
                 "{%0,%1,%2,%3},{%4,%5,%6,%7},{%8,%9},{%0,%1,%2,%3};" \
                 : "+f"((d)[0]), "+f"((d)[1]), "+f"((d)[2]), "+f"((d)[3]) \
                 : "r"((A)[0]), "r"((A)[1]), "r"((A)[2]), "r"((A)[3]), "r"(b0), "r"(b1))

#define CPASYNC16(dst, src) \
    asm volatile("cp.async.cg.shared.global [%0], [%1], 16;" :: "r"(dst), "l"(src) : "memory")
#define CPCOMMIT() asm volatile("cp.async.commit_group;" ::: "memory")
#define CPWAIT(n)  asm volatile("cp.async.wait_group %0;" :: "n"(n) : "memory")

__device__ __forceinline__ uint32_t bf2(float lo, float hi) {
    uint32_t r;
    asm("cvt.rn.bf16x2.f32 %0, %1, %2;" : "=r"(r) : "f"(hi), "f"(lo));
    return r;
}
__device__ __forceinline__ float bflo(uint32_t u) { return __uint_as_float(u << 16); }
__device__ __forceinline__ float bfhi(uint32_t u) { return __uint_as_float(u & 0xffff0000u); }

// fast exp: 2^f Taylor-6 + exponent splice (|rel|<2e-5 on [-4,4])
__device__ __forceinline__ float fexp(float x) {
    float t = x * 1.4426950408889634f;
    float fi = floorf(t);
    float f = t - fi;
    float p = 1.5403530e-4f;
    p = fmaf(p, f, 1.3333558e-3f);
    p = fmaf(p, f, 9.6181291e-3f);
    p = fmaf(p, f, 5.5504109e-2f);
    p = fmaf(p, f, 2.4022651e-1f);
    p = fmaf(p, f, 6.9314718e-1f);
    p = fmaf(p, f, 1.0f);
    return __int_as_float(__float_as_int(p) + (((int)fi) << 23));
}

__device__ __forceinline__ float shrinkf(float w) {
    float d = w - LAMBF;
    return fmaxf(d, 0.f) * w / (fabsf(d) + EPSS);
}

// ---------------- prologue: normalize memory + build swizzled operand tiles ----------------
__global__ void mm_prep(const float* __restrict__ mem, int M) {
    int m = blockIdx.x;
    int d = threadIdx.x;
    float v = (m < M) ? mem[(size_t)m * DD + d] : 0.f;
    float ss = v * v;
    #pragma unroll
    for (int o = 16; o; o >>= 1) ss += __shfl_xor_sync(0xffffffffu, ss, o);
    __shared__ float ws[8];
    __shared__ float sc;
    if ((d & 31) == 0) ws[d >> 5] = ss;
    __syncthreads();
    if (d == 0) {
        float t = 0.f;
        #pragma unroll
        for (int i = 0; i < 8; i++) t += ws[i];
        sc = sqrtf(t) + EPSN;
    }
    __syncthreads();
    g_mn[m * 256 + (((d >> 3) ^ (m & 7)) * 8) + (d & 7)] = __float2bfloat16(v / sc);
    int ch = m >> 6, c = m & 63;
    g_mt[ch * 16384 + d * 64 + (((c >> 3) ^ (d & 7)) * 8) + (c & 7)] = __float2bfloat16(v);
}

// ---------------- GEMM micro-kernels ----------------
__device__ __forceinline__ void gemm1(uint32_t sA, uint32_t sB, int wr, int wc, int lane,
                                      float acc[16]) {
    const uint32_t h = lane >> 4;
    const uint32_t arow = wr * 16 + (lane & 15);
    const uint32_t abase = sA + arow * 512;
    const uint32_t arx = arow & 7;
    const uint32_t brow = wc * 32 + (lane & 15);
    const uint32_t bbase = sB + brow * 512;
    const uint32_t brx = brow & 7;
    #pragma unroll
    for (int kk = 0; kk < 16; kk++) {
        uint32_t ca = ((uint32_t)(kk * 2 + h) ^ arx) << 4;
        uint32_t cb = ((uint32_t)(kk * 2 + h) ^ brx) << 4;
        uint32_t A[4], p0, p1, p2, p3, q0, q1, q2, q3;
        LDSM4(A[0], A[1], A[2], A[3], abase + ca);
        LDSM4(p0, p1, p2, p3, bbase + cb);
        LDSM4(q0, q1, q2, q3, bbase + 16 * 512 + cb);
        MMA16816(acc + 0,  A, p0, p2);
        MMA16816(acc + 4,  A, p1, p3);
        MMA16816(acc + 8,  A, q0, q2);
        MMA16816(acc + 12, A, q1, q3);
    }
}

__device__ __forceinline__ void gemm2(uint32_t sP, uint32_t sB2, int wr, int wc, int lane,
                                      float zac[64]) {
    const uint32_t h = lane >> 4;
    const uint32_t prow = wr * 16 + (lane & 15);
    const uint32_t pbase = sP + prow * 128;
    const uint32_t prx = prow & 7;
    const uint32_t drow = wc * 128 + (lane & 15);
    const uint32_t dbase = sB2 + drow * 128;
    const uint32_t drx = drow & 7;
    #pragma unroll
    for (int kk = 0; kk < 4; kk++) {
        uint32_t ca = ((uint32_t)(kk * 2 + h) ^ prx) << 4;
        uint32_t cb = ((uint32_t)(kk * 2 + h) ^ drx) << 4;
        uint32_t A[4];
        LDSM4(A[0], A[1], A[2], A[3], pbase + ca);
        #pragma unroll
        for (int g = 0; g < 8; g++) {
            uint32_t b0, b1, b2, b3;
            LDSM4(b0, b1, b2, b3, dbase + g * 2048 + cb);
            MMA16816(zac + (g * 2) * 4,     A, b0, b2);
            MMA16816(zac + (g * 2 + 1) * 4, A, b1, b3);
        }
    }
}

__device__ __forceinline__ void copyB(uint32_t sdst, const __nv_bfloat16* g) {
    const char* gp = (const char*)g;
    #pragma unroll
    for (int k = 0; k < 8; k++) {
        int idx = threadIdx.x + k * 256;
        CPASYNC16(sdst + idx * 16, gp + (size_t)idx * 16);
    }
}

// smem offsets (bytes)
// pass 1: A 0..32K, B dbl 32K..96K
#define A_OFF   0
#define B1A_OFF 32768
#define B1B_OFF 65536
// pass 2 (overlays pass-1 regions): sim dbl 0..16K, WB 16K..32K, MT 32K..64K,
//                                   LIST 64K..96K, P 96K..104K
#define SIMA    0
#define SIMB    8192
#define WB_OFF  16384
#define MT_OFF  32768
#define LIST_OFF 65536
#define P_OFF   98304
// persistent scratch
#define RED_OFF 106496     // 512 floats
#define ZS_OFF  108544
#define TS_OFF  108800
#define SS_OFF  109056
#define CNT_OFF 109312
#define SM_TOT  109568

__global__ __launch_bounds__(TPB, 2) void mm_main(
    const float* __restrict__ z,
    float* __restrict__ wout,     // [N, M]
    float* __restrict__ zhat,     // [N, 256]
    int M, int NCH)
{
    extern __shared__ char smc[];
    const uint32_t sbase = smem_u32(smc);
    const uint32_t sA = sbase + A_OFF;
    float* red  = (float*)(smc + RED_OFF);
    float* Zs   = (float*)(smc + ZS_OFF);
    float* Ts   = (float*)(smc + TS_OFF);
    float* Ss   = (float*)(smc + SS_OFF);
    int*   cntp = (int*)(smc + CNT_OFF);
    uint32_t* list = (uint32_t*)(smc + LIST_OFF);

    const int tid = threadIdx.x, wid = tid >> 5, lane = tid & 31;
    const int wr = wid >> 1, wc = wid & 1;
    const long long gr0 = (long long)blockIdx.x * RB;
    const int r0l = wr * 16 + (lane >> 2), r1l = r0l + 8;

    char* slice = (char*)(wout + gr0 * (long long)M);
    const int RSTR = 4 * M;        // bytes per w_hat row in slice
    const int SOFF = 2 * M;        // sim region offset within a row

    // ---- build A tile: normalize z rows, bf16, swizzled ----
    #pragma unroll 1
    for (int i = 0; i < 8; i++) {
        int r = wid * 8 + i;
        const float4* zr = (const float4*)(z + (gr0 + r) * DD);
        float4 a = zr[lane * 2], b = zr[lane * 2 + 1];
        float ss = a.x*a.x + a.y*a.y + a.z*a.z + a.w*a.w
                 + b.x*b.x + b.y*b.y + b.z*b.z + b.w*b.w;
        #pragma unroll
        for (int o = 16; o; o >>= 1) ss += __shfl_xor_sync(0xffffffffu, ss, o);
        float inv = 1.f / (sqrtf(ss) + EPSN);
        uint4 u;
        u.x = bf2(a.x * inv, a.y * inv); u.y = bf2(a.z * inv, a.w * inv);
        u.z = bf2(b.x * inv, b.y * inv); u.w = bf2(b.z * inv, b.w * inv);
        *(uint4*)(smc + A_OFF + r * 512 + ((lane ^ (r & 7)) * 16)) = u;
    }
    if (tid == 0) *cntp = 0;
    __syncthreads();

    // ================= PASS 1: GEMM1 once; Z; sim -> global (direct STG) =================
    float z0 = 0.f, z1 = 0.f;
    copyB(sbase + B1A_OFF, g_mn); CPCOMMIT();
    char* sim0 = slice + (size_t)r0l * RSTR + SOFF;
    char* sim1 = slice + (size_t)r1l * RSTR + SOFF;
    for (int ch = 0; ch < NCH; ch++) {
        __syncthreads();
        if (ch + 1 < NCH) copyB(sbase + (((ch + 1) & 1) ? B1B_OFF : B1A_OFF),
                                g_mn + (size_t)(ch + 1) * CH * DD);
        CPCOMMIT(); CPWAIT(1);
        __syncthreads();
        float acc[16] = {};
        gemm1(sA, sbase + ((ch & 1) ? B1B_OFF : B1A_OFF), wr, wc, lane, acc);
        #pragma unroll
        for (int nt = 0; nt < 4; nt++) {
            int cl  = wc * 32 + nt * 8 + 2 * (lane & 3);
            int col = ch * CH + cl;
            if (col < M) {  // M even, pair granularity
                *(uint32_t*)(sim0 + col * 2) = bf2(acc[nt * 4 + 0], acc[nt * 4 + 1]);
                *(uint32_t*)(sim1 + col * 2) = bf2(acc[nt * 4 + 2], acc[nt * 4 + 3]);
                z0 += fexp(acc[nt * 4 + 0]) + fexp(acc[nt * 4 + 1]);
                z1 += fexp(acc[nt * 4 + 2]) + fexp(acc[nt * 4 + 3]);
            }
        }
    }
    __threadfence();
    __syncthreads();
    red[r0l * 8 + wc * 4 + (lane & 3)] = z0;
    red[r1l * 8 + wc * 4 + (lane & 3)] = z1;
    __syncthreads();
    if (tid < 64) {
        float s = 0.f;
        #pragma unroll
        for (int j = 0; j < 8; j++) s += red[tid * 8 + j];
        Zs[tid] = 1.0f / s;
        Ts[tid] = logf(LAMBF * s) - 1e-3f;   // conservative skip threshold
    }
    __syncthreads();

    // ================= PASS 2: single sweep — w_hat (unnormalized) + S + sparse GEMM2 ===
    const int rS = tid >> 2;
    const float invZr = Zs[rS], Tr = Ts[rS];
    float sacc = 0.f;
    float zac[64] = {};
    {
        #pragma unroll
        for (int k = 0; k < 2; k++) {
            int idx = tid + k * 256;
            int r = idx >> 3, g = idx & 7;
            if (g * 16 < SOFF)
                CPASYNC16(sbase + SIMA + idx * 16, slice + (size_t)r * RSTR + SOFF + g * 16);
        }
        CPCOMMIT();
    }
    for (int ch = 0; ch < NCH; ch++) {
        __syncthreads();
        if (ch + 1 < NCH) {
            #pragma unroll
            for (int k = 0; k < 2; k++) {
                int idx = tid + k * 256;
                int r = idx >> 3, g = idx & 7;
                int off = (ch + 1) * 128 + g * 16;
                if (off < SOFF)
                    CPASYNC16(sbase + (((ch + 1) & 1) ? SIMB : SIMA) + idx * 16,
                              slice + (size_t)r * RSTR + SOFF + off);
            }
        }
        CPCOMMIT(); CPWAIT(1);
        __syncthreads();

        float h0[8], h1[8];
        int rare = 0;
        {
            const uint32_t sb = sbase + ((ch & 1) ? SIMB : SIMA) + rS * 128 + (tid & 3) * 32;
            uint32_t v[8];
            #pragma unroll
            for (int q = 0; q < 2; q++) {
                uint4 u; asm volatile("ld.shared.v4.u32 {%0,%1,%2,%3}, [%4];"
                    : "=r"(u.x), "=r"(u.y), "=r"(u.z), "=r"(u.w) : "r"(sb + q * 16));
                v[q*4]=u.x; v[q*4+1]=u.y; v[q*4+2]=u.z; v[q*4+3]=u.w;
            }
            #pragma unroll
            for (int j = 0; j < 8; j++) {
                int cl  = (tid & 3) * 16 + 2 * j;
                int col = ch * CH + cl;
                float lo = bflo(v[j]), hi = bfhi(v[j]);
                h0[j] = 0.f; h1[j] = 0.f;
                if (col < M && lo > Tr) {
                    h0[j] = shrinkf(fexp(lo) * invZr);
                    sacc += h0[j]; rare = 1;
                    int ix = atomicAdd(cntp, 1);
                    if (ix < LCAP) list[ix] = ((uint32_t)rS << 16) | (uint32_t)col;
                }
                if (col + 1 < M && hi > Tr) {
                    h1[j] = shrinkf(fexp(hi) * invZr);
                    sacc += h1[j]; rare = 1;
                    int ix = atomicAdd(cntp, 1);
                    if (ix < LCAP) list[ix] = ((uint32_t)rS << 16) | (uint32_t)(col + 1);
                }
            }
        }
        const int flag = __syncthreads_or(rare);   // uniform
        if (flag) {
            // stage WB (fp32 h) + P (bf16 h) and run GEMM2 for this chunk
            #pragma unroll
            for (int j = 0; j < 8; j++) {
                int cl = (tid & 3) * 16 + 2 * j;
                *(uint32_t*)(smc + P_OFF + rS * 128 + (((cl >> 3) ^ (rS & 7)) << 4) + (cl & 7) * 2)
                    = bf2(h0[j], h1[j]);
                *(float2*)(smc + WB_OFF + rS * 256 + (((cl >> 2) ^ (rS & 7)) << 4) + (cl & 3) * 4)
                    = make_float2(h0[j], h1[j]);
            }
            __syncthreads();
            copyB(sbase + MT_OFF, g_mt + (size_t)ch * CH * DD);
            CPCOMMIT(); CPWAIT(0);
            __syncthreads();
            gemm2(sbase + P_OFF, sbase + MT_OFF, wr, wc, lane, zac);
        }
        // copy-out w_hat chunk (h values; zeros on common path)
        #pragma unroll
        for (int k = 0; k < 4; k++) {
            int idx = tid + k * 256;
            int r = idx >> 4, j = idx & 15;
            int col = ch * CH + j * 4;
            if (col < M) {
                uint4 v;
                if (flag) v = *(uint4*)(smc + WB_OFF + r * 256 + ((j ^ (r & 7)) << 4));
                else      v = make_uint4(0u, 0u, 0u, 0u);
                *(uint4*)(wout + (gr0 + r) * (long long)M + col) = v;
            }
        }
    }

    // ---- S reduction ----
    __syncthreads();
    red[tid] = sacc;
    __syncthreads();
    if (tid < 64)
        Ss[tid] = 1.0f / (red[4 * tid] + red[4 * tid + 1] + red[4 * tid + 2] + red[4 * tid + 3] + EPSS);
    __syncthreads();

    // ---- sparse fixup: scale recorded nonzeros by invS (or full rescale on overflow) ----
    {
        int total = *cntp;
        if (total <= LCAP) {
            for (int i = tid; i < total; i += TPB) {
                uint32_t e = list[i];
                int r = (int)(e >> 16), c = (int)(e & 0xffffu);
                float* p = wout + (gr0 + r) * (long long)M + c;
                *p *= Ss[r];
            }
        } else {
            const int Q = M >> 2;
            for (int idx = tid; idx < RB * Q; idx += TPB) {
                int r = idx / Q, c4 = (idx - r * Q) * 4;
                float4* p = (float4*)(wout + (gr0 + r) * (long long)M + c4);
                float4 v = *p; float s = Ss[r];
                v.x *= s; v.y *= s; v.z *= s; v.w *= s;
                *p = v;
            }
        }
    }

    // ---- z_hat epilogue ----
    {
        const float invS0 = Ss[r0l], invS1 = Ss[r1l];
        float* zr0 = zhat + (gr0 + r0l) * DD;
        float* zr1 = zhat + (gr0 + r1l) * DD;
        #pragma unroll
        for (int g = 0; g < 8; g++) {
            #pragma unroll
            for (int t = 0; t < 2; t++) {
                int d = wc * 128 + g * 16 + t * 8 + 2 * (lane & 3);
                int ii = (g * 2 + t) * 4;
                *(float2*)(zr0 + d) = make_float2(zac[ii + 0] * invS0, zac[ii + 1] * invS0);
                *(float2*)(zr1 + d) = make_float2(zac[ii + 2] * invS1, zac[ii + 3] * invS1);
            }
        }
    }
}

// ---------------- host ----------------
extern "C" void kernel_launch(void* const* d_in, const int* in_sizes, int n_in,
                              void* d_out, int out_size) {
    const float* z   = (const float*)d_in[0];
    const float* mem = (const float*)d_in[1];
    const int N = in_sizes[0] / DD;
    const int M = in_sizes[1] / DD;
    const int NCH = (M + CH - 1) / CH;

    float* zhat = (float*)d_out;                 // [N, 256]
    float* wout = zhat + (size_t)N * DD;         // [N, M]

    cudaFuncSetAttribute(mm_main, cudaFuncAttributeMaxDynamicSharedMemorySize, SM_TOT);

    mm_prep<<<NCH * CH, 256>>>(mem, M);
    mm_main<<<N / RB, TPB, SM_TOT>>>(z, wout, zhat, M, NCH);
}

// round 7
// speedup vs baseline: 18.9558x; 1.2806x over previous
#include <cuda_runtime.h>
#include <cuda_bf16.h>
#include <math.h>
#include <stdint.h>

#define DD    256
#define RB    64          // z rows per CTA
#define CH    64          // memory cols per chunk
#define TPB   256
#define LAMBF 0.002f
#define EPSN  1e-10f
#define EPSS  1e-12f
#define MAXM  2048
#define NCHMX 32

// pre-swizzled bf16 operand tiles (scratch via __device__ globals)
__device__ __align__(16) __nv_bfloat16 g_mn[MAXM * DD];   // m_norm rows, ldmatrix swizzle
__device__ __align__(16) __nv_bfloat16 g_mt[MAXM * DD];   // mem^T chunk-blocked, ldmatrix swizzle

// ---------------- helpers ----------------
__device__ __forceinline__ uint32_t smem_u32(const void* p) {
    uint32_t a;
    asm("{ .reg .u64 t; cvta.to.shared.u64 t, %1; cvt.u32.u64 %0, t; }" : "=r"(a) : "l"(p));
    return a;
}

#define LDSM4(r0, r1, r2, r3, a) \
    asm volatile("ldmatrix.sync.aligned.m8n8.x4.shared.b16 {%0,%1,%2,%3}, [%4];" \
                 : "=r"(r0), "=r"(r1), "=r"(r2), "=r"(r3) : "r"(a))

#define MMA16816(d, A, b0, b1) \
    asm volatile("mma.sync.aligned.m16n8k16.row.col.f32.bf16.bf16.f32 " \
                 "{%0,%1,%2,%3},{%4,%5,%6,%7},{%8,%9},{%0,%1,%2,%3};" \
                 : "+f"((d)[0]), "+f"((d)[1]), "+f"((d)[2]), "+f"((d)[3]) \
                 : "r"((A)[0]), "r"((A)[1]), "r"((A)[2]), "r"((A)[3]), "r"(b0), "r"(b1))

#define CPASYNC16(dst, src) \
    asm volatile("cp.async.cg.shared.global [%0], [%1], 16;" :: "r"(dst), "l"(src) : "memory")
#define CPCOMMIT() asm volatile("cp.async.commit_group;" ::: "memory")
#define CPWAIT(n)  asm volatile("cp.async.wait_group %0;" :: "n"(n) : "memory")

__device__ __forceinline__ uint32_t bf2(float lo, float hi) {
    uint32_t r;
    asm("cvt.rn.bf16x2.f32 %0, %1, %2;" : "=r"(r) : "f"(hi), "f"(lo));
    return r;
}

// order-preserving float->uint encode (for atomicMax on signed floats)
__device__ __forceinline__ uint32_t encf(float x) {
    uint32_t u = __float_as_uint(x);
    return (u & 0x80000000u) ? ~u : (u | 0x80000000u);
}

// fast exp: 2^f Taylor-6 + exponent splice (|rel|<2e-5 on [-4,4])
__device__ __forceinline__ float fexp(float x) {
    float t = x * 1.4426950408889634f;
    float fi = floorf(t);
    float f = t - fi;
    float p = 1.5403530e-4f;
    p = fmaf(p, f, 1.3333558e-3f);
    p = fmaf(p, f, 9.6181291e-3f);
    p = fmaf(p, f, 5.5504109e-2f);
    p = fmaf(p, f, 2.4022651e-1f);
    p = fmaf(p, f, 6.9314718e-1f);
    p = fmaf(p, f, 1.0f);
    return __int_as_float(__float_as_int(p) + (((int)fi) << 23));
}

__device__ __forceinline__ float shrinkf(float w) {
    float d = w - LAMBF;
    return fmaxf(d, 0.f) * w / (fabsf(d) + EPSS);
}

// ---------------- prologue: normalize memory + build swizzled operand tiles ----------------
__global__ void mm_prep(const float* __restrict__ mem, int M) {
    int m = blockIdx.x;
    int d = threadIdx.x;
    float v = (m < M) ? mem[(size_t)m * DD + d] : 0.f;
    float ss = v * v;
    #pragma unroll
    for (int o = 16; o; o >>= 1) ss += __shfl_xor_sync(0xffffffffu, ss, o);
    __shared__ float ws[8];
    __shared__ float sc;
    if ((d & 31) == 0) ws[d >> 5] = ss;
    __syncthreads();
    if (d == 0) {
        float t = 0.f;
        #pragma unroll
        for (int i = 0; i < 8; i++) t += ws[i];
        sc = sqrtf(t) + EPSN;
    }
    __syncthreads();
    g_mn[m * 256 + (((d >> 3) ^ (m & 7)) * 8) + (d & 7)] = __float2bfloat16(v / sc);
    int ch = m >> 6, c = m & 63;
    g_mt[ch * 16384 + d * 64 + (((c >> 3) ^ (d & 7)) * 8) + (c & 7)] = __float2bfloat16(v);
}

// ---------------- GEMM micro-kernels ----------------
// pass-1 variant: A fragments resident in registers
__device__ __forceinline__ void gemm1_reg(const uint32_t* Areg, uint32_t sB, int wc, int lane,
                                          float acc[16]) {
    const uint32_t h = lane >> 4;
    const uint32_t brow = wc * 32 + (lane & 15);
    const uint32_t bbase = sB + brow * 512;
    const uint32_t brx = brow & 7;
    #pragma unroll
    for (int kk = 0; kk < 16; kk++) {
        uint32_t cb = ((uint32_t)(kk * 2 + h) ^ brx) << 4;
        uint32_t p0, p1, p2, p3, q0, q1, q2, q3;
        LDSM4(p0, p1, p2, p3, bbase + cb);
        LDSM4(q0, q1, q2, q3, bbase + 16 * 512 + cb);
        MMA16816(acc + 0,  (Areg + 4 * kk), p0, p2);
        MMA16816(acc + 4,  (Areg + 4 * kk), p1, p3);
        MMA16816(acc + 8,  (Areg + 4 * kk), q0, q2);
        MMA16816(acc + 12, (Areg + 4 * kk), q1, q3);
    }
}

// phase-A variant: A from SMEM (register pressure lower here)
__device__ __forceinline__ void gemm1(uint32_t sA, uint32_t sB, int wr, int wc, int lane,
                                      float acc[16]) {
    const uint32_t h = lane >> 4;
    const uint32_t arow = wr * 16 + (lane & 15);
    const uint32_t abase = sA + arow * 512;
    const uint32_t arx = arow & 7;
    const uint32_t brow = wc * 32 + (lane & 15);
    const uint32_t bbase = sB + brow * 512;
    const uint32_t brx = brow & 7;
    #pragma unroll
    for (int kk = 0; kk < 16; kk++) {
        uint32_t ca = ((uint32_t)(kk * 2 + h) ^ arx) << 4;
        uint32_t cb = ((uint32_t)(kk * 2 + h) ^ brx) << 4;
        uint32_t A[4], p0, p1, p2, p3, q0, q1, q2, q3;
        LDSM4(A[0], A[1], A[2], A[3], abase + ca);
        LDSM4(p0, p1, p2, p3, bbase + cb);
        LDSM4(q0, q1, q2, q3, bbase + 16 * 512 + cb);
        MMA16816(acc + 0,  A, p0, p2);
        MMA16816(acc + 4,  A, p1, p3);
        MMA16816(acc + 8,  A, q0, q2);
        MMA16816(acc + 12, A, q1, q3);
    }
}

__device__ __forceinline__ void gemm2(uint32_t sP, uint32_t sB2, int wr, int wc, int lane,
                                      float zac[64]) {
    const uint32_t h = lane >> 4;
    const uint32_t prow = wr * 16 + (lane & 15);
    const uint32_t pbase = sP + prow * 128;
    const uint32_t prx = prow & 7;
    const uint32_t drow = wc * 128 + (lane & 15);
    const uint32_t dbase = sB2 + drow * 128;
    const uint32_t drx = drow & 7;
    #pragma unroll
    for (int kk = 0; kk < 4; kk++) {
        uint32_t ca = ((uint32_t)(kk * 2 + h) ^ prx) << 4;
        uint32_t cb = ((uint32_t)(kk * 2 + h) ^ drx) << 4;
        uint32_t A[4];
        LDSM4(A[0], A[1], A[2], A[3], pbase + ca);
        #pragma unroll
        for (int g = 0; g < 8; g++) {
            uint32_t b0, b1, b2, b3;
            LDSM4(b0, b1, b2, b3, dbase + g * 2048 + cb);
            MMA16816(zac + (g * 2) * 4,     A, b0, b2);
            MMA16816(zac + (g * 2 + 1) * 4, A, b1, b3);
        }
    }
}

__device__ __forceinline__ void copyB(uint32_t sdst, const __nv_bfloat16* g) {
    const char* gp = (const char*)g;
    #pragma unroll
    for (int k = 0; k < 8; k++) {
        int idx = threadIdx.x + k * 256;
        CPASYNC16(sdst + idx * 16, gp + (size_t)idx * 16);
    }
}

// smem offsets (bytes)
#define A_OFF    0          // A tile, resident through phase A (32K)
#define B1A_OFF  32768      // pass1 B dbl / phase A B1 tile
#define B1B_OFF  65536      // pass1 B dbl / phase A memT tile
#define RMAX_OFF 98304      // 32 chunks x 64 rows x 4B = 8K; phase A: P tile
#define P_OFF    98304
#define TENC_OFF 106496     // 64 x 4B
#define FLG_OFF  106752     // 32 x 4B
#define RED_OFF  106880     // 512 floats
#define ZS_OFF   108928
#define TS_OFF   109184
#define SS_OFF   109440
#define SM_TOT   109696

__global__ __launch_bounds__(TPB, 2) void mm_main(
    const float* __restrict__ z,
    float* __restrict__ wout,     // [N, M]
    float* __restrict__ zhat,     // [N, 256]
    int M, int NCH)
{
    extern __shared__ char smc[];
    const uint32_t sbase = smem_u32(smc);
    const uint32_t sA = sbase + A_OFF;
    uint32_t* rmax = (uint32_t*)(smc + RMAX_OFF);
    uint32_t* tenc = (uint32_t*)(smc + TENC_OFF);
    int*      flg  = (int*)(smc + FLG_OFF);
    float*    red  = (float*)(smc + RED_OFF);
    float*    Zs   = (float*)(smc + ZS_OFF);
    float*    Ts   = (float*)(smc + TS_OFF);
    float*    Ss   = (float*)(smc + SS_OFF);

    const int tid = threadIdx.x, wid = tid >> 5, lane = tid & 31;
    const int wr = wid >> 1, wc = wid & 1;
    const long long gr0 = (long long)blockIdx.x * RB;
    const int r0l = wr * 16 + (lane >> 2), r1l = r0l + 8;

    // ---- init rmax, build A tile ----
    for (int i = tid; i < NCH * 64; i += TPB) rmax[i] = 0u;
    #pragma unroll 1
    for (int i = 0; i < 8; i++) {
        int r = wid * 8 + i;
        const float4* zr = (const float4*)(z + (gr0 + r) * DD);
        float4 a = zr[lane * 2], b = zr[lane * 2 + 1];
        float ss = a.x*a.x + a.y*a.y + a.z*a.z + a.w*a.w
                 + b.x*b.x + b.y*b.y + b.z*b.z + b.w*b.w;
        #pragma unroll
        for (int o = 16; o; o >>= 1) ss += __shfl_xor_sync(0xffffffffu, ss, o);
        float inv = 1.f / (sqrtf(ss) + EPSN);
        uint4 u;
        u.x = bf2(a.x * inv, a.y * inv); u.y = bf2(a.z * inv, a.w * inv);
        u.z = bf2(b.x * inv, b.y * inv); u.w = bf2(b.z * inv, b.w * inv);
        *(uint4*)(smc + A_OFF + r * 512 + ((lane ^ (r & 7)) * 16)) = u;
    }
    __syncthreads();

    // ---- hoist A fragments to registers (pass 1 only) ----
    uint32_t Areg[64];
    {
        const uint32_t h = lane >> 4;
        const uint32_t arow = wr * 16 + (lane & 15);
        const uint32_t abase = sA + arow * 512;
        const uint32_t arx = arow & 7;
        #pragma unroll
        for (int kk = 0; kk < 16; kk++) {
            uint32_t ca = ((uint32_t)(kk * 2 + h) ^ arx) << 4;
            LDSM4(Areg[4*kk], Areg[4*kk+1], Areg[4*kk+2], Areg[4*kk+3], abase + ca);
        }
    }

    // ================= PASS 1: GEMM1; Z; per-(row,chunk) max =================
    float z0 = 0.f, z1 = 0.f;
    copyB(sbase + B1A_OFF, g_mn); CPCOMMIT();
    for (int ch = 0; ch < NCH; ch++) {
        __syncthreads();
        if (ch + 1 < NCH) copyB(sbase + (((ch + 1) & 1) ? B1B_OFF : B1A_OFF),
                                g_mn + (size_t)(ch + 1) * CH * DD);
        CPCOMMIT(); CPWAIT(1);
        __syncthreads();
        float acc[16] = {};
        gemm1_reg(Areg, sbase + ((ch & 1) ? B1B_OFF : B1A_OFF), wc, lane, acc);
        float m0 = -3.f, m1 = -3.f;
        #pragma unroll
        for (int nt = 0; nt < 4; nt++) {
            int col = ch * CH + wc * 32 + nt * 8 + 2 * (lane & 3);
            if (col < M) {   // M even: pair fully valid
                z0 += fexp(acc[nt * 4 + 0]) + fexp(acc[nt * 4 + 1]);
                z1 += fexp(acc[nt * 4 + 2]) + fexp(acc[nt * 4 + 3]);
                m0 = fmaxf(m0, fmaxf(acc[nt * 4 + 0], acc[nt * 4 + 1]));
                m1 = fmaxf(m1, fmaxf(acc[nt * 4 + 2], acc[nt * 4 + 3]));
            }
        }
        if (m0 > -3.f) atomicMax(&rmax[ch * 64 + r0l], encf(m0));
        if (m1 > -3.f) atomicMax(&rmax[ch * 64 + r1l], encf(m1));
    }
    __syncthreads();
    red[r0l * 8 + wc * 4 + (lane & 3)] = z0;
    red[r1l * 8 + wc * 4 + (lane & 3)] = z1;
    __syncthreads();
    if (tid < 64) {
        float s = 0.f;
        #pragma unroll
        for (int j = 0; j < 8; j++) s += red[tid * 8 + j];
        Zs[tid] = 1.0f / s;
        float T = logf(LAMBF * s) - 1e-3f;   // conservative skip threshold
        Ts[tid] = T;
        tenc[tid] = encf(T);
    }
    __syncthreads();
    // chunk flags
    if (tid < NCH) {
        int f = 0;
        #pragma unroll 4
        for (int r = 0; r < 64; r++) f |= (rmax[tid * 64 + r] > tenc[r]);
        flg[tid] = f;
    }
    __syncthreads();

    // ================= PHASE A (rare): flagged chunks =================
    const float invZ0 = Zs[r0l], invZ1 = Zs[r1l];
    const float T0 = Ts[r0l],    T1 = Ts[r1l];
    float s0 = 0.f, s1 = 0.f;
    float zac[64] = {};
    int any = 0;
    for (int ch = 0; ch < NCH; ch++) {
        if (!flg[ch]) continue;
        any = 1;
        copyB(sbase + B1A_OFF, g_mn + (size_t)ch * CH * DD);
        CPCOMMIT(); CPWAIT(0);
        __syncthreads();
        float acc[16] = {};
        gemm1(sA, sbase + B1A_OFF, wr, wc, lane, acc);
        float* w0 = wout + (gr0 + r0l) * (long long)M;
        float* w1 = wout + (gr0 + r1l) * (long long)M;
        #pragma unroll
        for (int nt = 0; nt < 4; nt++) {
            int cl  = wc * 32 + nt * 8 + 2 * (lane & 3);
            int col = ch * CH + cl;
            float h00 = 0.f, h01 = 0.f, h10 = 0.f, h11 = 0.f;
            if (col < M) {
                float a0 = acc[nt*4+0], a1 = acc[nt*4+1], a2 = acc[nt*4+2], a3 = acc[nt*4+3];
                if (a0 > T0) h00 = shrinkf(fexp(a0) * invZ0);
                if (a1 > T0) h01 = shrinkf(fexp(a1) * invZ0);
                if (a2 > T1) h10 = shrinkf(fexp(a2) * invZ1);
                if (a3 > T1) h11 = shrinkf(fexp(a3) * invZ1);
                s0 += h00 + h01; s1 += h10 + h11;
                *(float2*)(w0 + col) = make_float2(h00, h01);   // unnormalized; fixed up later
                *(float2*)(w1 + col) = make_float2(h10, h11);
            }
            *(uint32_t*)(smc + P_OFF + r0l * 128 + (((cl >> 3) ^ (r0l & 7)) << 4) + (cl & 7) * 2)
                = bf2(h00, h01);
            *(uint32_t*)(smc + P_OFF + r1l * 128 + (((cl >> 3) ^ (r1l & 7)) << 4) + (cl & 7) * 2)
                = bf2(h10, h11);
        }
        __syncthreads();
        copyB(sbase + B1B_OFF, g_mt + (size_t)ch * CH * DD);
        CPCOMMIT(); CPWAIT(0);
        __syncthreads();
        gemm2(sbase + P_OFF, sbase + B1B_OFF, wr, wc, lane, zac);
        __syncthreads();
    }

    // ---- S reduction ----
    red[r0l * 8 + wc * 4 + (lane & 3)] = s0;
    red[r1l * 8 + wc * 4 + (lane & 3)] = s1;
    __syncthreads();
    if (tid < 64) {
        float s = 0.f;
        #pragma unroll
        for (int j = 0; j < 8; j++) s += red[tid * 8 + j];
        Ss[tid] = 1.0f / (s + EPSS);
    }
    __syncthreads();

    // ---- fixup flagged chunks: w_hat *= invS ----
    if (any) {
        for (int ch = 0; ch < NCH; ch++) {
            if (!flg[ch]) continue;
            for (int idx = tid; idx < 64 * 16; idx += TPB) {
                int r = idx >> 4;
                int c4 = ch * CH + (idx & 15) * 4;
                if (c4 < M) {
                    float4* p = (float4*)(wout + (gr0 + r) * (long long)M + c4);
                    float4 v = *p; float s = Ss[r];
                    v.x *= s; v.y *= s; v.z *= s; v.w *= s;
                    *p = v;
                }
            }
        }
        __syncthreads();
    }

    // ---- zero-fill unflagged chunks of w_hat ----
    {
        const int Q = M >> 2;       // M % 4 == 0
        const float4 zero4 = make_float4(0.f, 0.f, 0.f, 0.f);
        #pragma unroll 1
        for (int r = 0; r < RB; r++) {
            float4* row = (float4*)(wout + (gr0 + r) * (long long)M);
            for (int c = tid; c < Q; c += TPB)
                if (!flg[(c * 4) >> 6]) row[c] = zero4;
        }
    }

    // ---- z_hat epilogue ----
    {
        const float invS0 = Ss[r0l], invS1 = Ss[r1l];
        float* zr0 = zhat + (gr0 + r0l) * DD;
        float* zr1 = zhat + (gr0 + r1l) * DD;
        #pragma unroll
        for (int g = 0; g < 8; g++) {
            #pragma unroll
            for (int t = 0; t < 2; t++) {
                int d = wc * 128 + g * 16 + t * 8 + 2 * (lane & 3);
                int ii = (g * 2 + t) * 4;
                *(float2*)(zr0 + d) = make_float2(zac[ii + 0] * invS0, zac[ii + 1] * invS0);
                *(float2*)(zr1 + d) = make_float2(zac[ii + 2] * invS1, zac[ii + 3] * invS1);
            }
        }
    }
}

// ---------------- host ----------------
extern "C" void kernel_launch(void* const* d_in, const int* in_sizes, int n_in,
                              void* d_out, int out_size) {
    const float* z   = (const float*)d_in[0];
    const float* mem = (const float*)d_in[1];
    const int N = in_sizes[0] / DD;
    const int M = in_sizes[1] / DD;
    const int NCH = (M + CH - 1) / CH;

    float* zhat = (float*)d_out;                 // [N, 256]
    float* wout = zhat + (size_t)N * DD;         // [N, M]

    cudaFuncSetAttribute(mm_main, cudaFuncAttributeMaxDynamicSharedMemorySize, SM_TOT);

    mm_prep<<<NCH * CH, 256>>>(mem, M);
    mm_main<<<N / RB, TPB, SM_TOT>>>(z, wout, zhat, M, NCH);
}

// round 8
// speedup vs baseline: 22.0791x; 1.1648x over previous
#include <cuda_runtime.h>
#include <cuda_bf16.h>
#include <math.h>
#include <stdint.h>

#define DD    256
#define RB    64          // z rows per CTA
#define CH    64          // memory cols per chunk
#define TPB   256
#define LAMBF 0.002f
#define EPSN  1e-10f
#define EPSS  1e-12f
#define MAXM  2048
#define NCHMX 32

// pre-swizzled bf16 operand tiles (scratch via __device__ globals)
__device__ __align__(16) __nv_bfloat16 g_mn[MAXM * DD];   // m_norm rows, ldmatrix swizzle
__device__ __align__(16) __nv_bfloat16 g_mt[MAXM * DD];   // mem^T chunk-blocked, ldmatrix swizzle

// ---------------- helpers ----------------
__device__ __forceinline__ uint32_t smem_u32(const void* p) {
    uint32_t a;
    asm("{ .reg .u64 t; cvta.to.shared.u64 t, %1; cvt.u32.u64 %0, t; }" : "=r"(a) : "l"(p));
    return a;
}

#define LDSM4(r0, r1, r2, r3, a) \
    asm volatile("ldmatrix.sync.aligned.m8n8.x4.shared.b16 {%0,%1,%2,%3}, [%4];" \
                 : "=r"(r0), "=r"(r1), "=r"(r2), "=r"(r3) : "r"(a))

#define MMA16816(d, A, b0, b1) \
    asm volatile("mma.sync.aligned.m16n8k16.row.col.f32.bf16.bf16.f32 " \
                 "{%0,%1,%2,%3},{%4,%5,%6,%7},{%8,%9},{%0,%1,%2,%3};" \
                 : "+f"((d)[0]), "+f"((d)[1]), "+f"((d)[2]), "+f"((d)[3]) \
                 : "r"((A)[0]), "r"((A)[1]), "r"((A)[2]), "r"((A)[3]), "r"(b0), "r"(b1))

#define CPASYNC16(dst, src) \
    asm volatile("cp.async.cg.shared.global [%0], [%1], 16;" :: "r"(dst), "l"(src) : "memory")
#define CPCOMMIT() asm volatile("cp.async.commit_group;" ::: "memory")
#define CPWAIT(n)  asm volatile("cp.async.wait_group %0;" :: "n"(n) : "memory")

__device__ __forceinline__ uint32_t bf2(float lo, float hi) {
    uint32_t r;
    asm("cvt.rn.bf16x2.f32 %0, %1, %2;" : "=r"(r) : "f"(hi), "f"(lo));
    return r;
}

// order-preserving float->uint encode (for atomicMax on signed floats)
__device__ __forceinline__ uint32_t encf(float x) {
    uint32_t u = __float_as_uint(x);
    return (u & 0x80000000u) ? ~u : (u | 0x80000000u);
}

// fast exp: 2^f Taylor-6 + exponent splice (|rel|<2e-5 on [-4,4]); fexp(0)==1.0f exactly
__device__ __forceinline__ float fexp(float x) {
    float t = x * 1.4426950408889634f;
    float fi = floorf(t);
    float f = t - fi;
    float p = 1.5403530e-4f;
    p = fmaf(p, f, 1.3333558e-3f);
    p = fmaf(p, f, 9.6181291e-3f);
    p = fmaf(p, f, 5.5504109e-2f);
    p = fmaf(p, f, 2.4022651e-1f);
    p = fmaf(p, f, 6.9314718e-1f);
    p = fmaf(p, f, 1.0f);
    return __int_as_float(__float_as_int(p) + (((int)fi) << 23));
}

__device__ __forceinline__ float shrinkf(float w) {
    float d = w - LAMBF;
    return fmaxf(d, 0.f) * w / (fabsf(d) + EPSS);
}

// ---------------- prologue: normalize memory + build swizzled operand tiles ----------------
__global__ void mm_prep(const float* __restrict__ mem, int M) {
    int m = blockIdx.x;
    int d = threadIdx.x;
    float v = (m < M) ? mem[(size_t)m * DD + d] : 0.f;
    float ss = v * v;
    #pragma unroll
    for (int o = 16; o; o >>= 1) ss += __shfl_xor_sync(0xffffffffu, ss, o);
    __shared__ float ws[8];
    __shared__ float sc;
    if ((d & 31) == 0) ws[d >> 5] = ss;
    __syncthreads();
    if (d == 0) {
        float t = 0.f;
        #pragma unroll
        for (int i = 0; i < 8; i++) t += ws[i];
        sc = sqrtf(t) + EPSN;
    }
    __syncthreads();
    g_mn[m * 256 + (((d >> 3) ^ (m & 7)) * 8) + (d & 7)] = __float2bfloat16(v / sc);
    int ch = m >> 6, c = m & 63;
    g_mt[ch * 16384 + d * 64 + (((c >> 3) ^ (d & 7)) * 8) + (c & 7)] = __float2bfloat16(v);
}

// ---------------- GEMM micro-kernels ----------------
__device__ __forceinline__ void gemm1_reg(const uint32_t* Areg, uint32_t sB, int wc, int lane,
                                          float acc[16]) {
    const uint32_t h = lane >> 4;
    const uint32_t brow = wc * 32 + (lane & 15);
    const uint32_t bbase = sB + brow * 512;
    const uint32_t brx = brow & 7;
    #pragma unroll
    for (int kk = 0; kk < 16; kk++) {
        uint32_t cb = ((uint32_t)(kk * 2 + h) ^ brx) << 4;
        uint32_t p0, p1, p2, p3, q0, q1, q2, q3;
        LDSM4(p0, p1, p2, p3, bbase + cb);
        LDSM4(q0, q1, q2, q3, bbase + 16 * 512 + cb);
        MMA16816(acc + 0,  (Areg + 4 * kk), p0, p2);
        MMA16816(acc + 4,  (Areg + 4 * kk), p1, p3);
        MMA16816(acc + 8,  (Areg + 4 * kk), q0, q2);
        MMA16816(acc + 12, (Areg + 4 * kk), q1, q3);
    }
}

__device__ __forceinline__ void gemm1(uint32_t sA, uint32_t sB, int wr, int wc, int lane,
                                      float acc[16]) {
    const uint32_t h = lane >> 4;
    const uint32_t arow = wr * 16 + (lane & 15);
    const uint32_t abase = sA + arow * 512;
    const uint32_t arx = arow & 7;
    const uint32_t brow = wc * 32 + (lane & 15);
    const uint32_t bbase = sB + brow * 512;
    const uint32_t brx = brow & 7;
    #pragma unroll
    for (int kk = 0; kk < 16; kk++) {
        uint32_t ca = ((uint32_t)(kk * 2 + h) ^ arx) << 4;
        uint32_t cb = ((uint32_t)(kk * 2 + h) ^ brx) << 4;
        uint32_t A[4], p0, p1, p2, p3, q0, q1, q2, q3;
        LDSM4(A[0], A[1], A[2], A[3], abase + ca);
        LDSM4(p0, p1, p2, p3, bbase + cb);
        LDSM4(q0, q1, q2, q3, bbase + 16 * 512 + cb);
        MMA16816(acc + 0,  A, p0, p2);
        MMA16816(acc + 4,  A, p1, p3);
        MMA16816(acc + 8,  A, q0, q2);
        MMA16816(acc + 12, A, q1, q3);
    }
}

__device__ __forceinline__ void gemm2(uint32_t sP, uint32_t sB2, int wr, int wc, int lane,
                                      float zac[64]) {
    const uint32_t h = lane >> 4;
    const uint32_t prow = wr * 16 + (lane & 15);
    const uint32_t pbase = sP + prow * 128;
    const uint32_t prx = prow & 7;
    const uint32_t drow = wc * 128 + (lane & 15);
    const uint32_t dbase = sB2 + drow * 128;
    const uint32_t drx = drow & 7;
    #pragma unroll
    for (int kk = 0; kk < 4; kk++) {
        uint32_t ca = ((uint32_t)(kk * 2 + h) ^ prx) << 4;
        uint32_t cb = ((uint32_t)(kk * 2 + h) ^ drx) << 4;
        uint32_t A[4];
        LDSM4(A[0], A[1], A[2], A[3], pbase + ca);
        #pragma unroll
        for (int g = 0; g < 8; g++) {
            uint32_t b0, b1, b2, b3;
            LDSM4(b0, b1, b2, b3, dbase + g * 2048 + cb);
            MMA16816(zac + (g * 2) * 4,     A, b0, b2);
            MMA16816(zac + (g * 2 + 1) * 4, A, b1, b3);
        }
    }
}

__device__ __forceinline__ void copyB(uint32_t sdst, const __nv_bfloat16* g) {
    const char* gp = (const char*)g;
    #pragma unroll
    for (int k = 0; k < 8; k++) {
        int idx = threadIdx.x + k * 256;
        CPASYNC16(sdst + idx * 16, gp + (size_t)idx * 16);
    }
}

// smem offsets (bytes)
#define A_OFF    0          // A tile, resident through phase A (32K)
#define B1A_OFF  32768      // pass1 B dbl / phase A B1 tile
#define B1B_OFF  65536      // pass1 B dbl / phase A memT tile
#define RMAX_OFF 98304      // 32 chunks x 64 rows x 4B = 8K; phase A: P tile
#define P_OFF    98304
#define TENC_OFF 106496     // 64 x 4B
#define FLG_OFF  106752     // 32 x 4B
#define RED_OFF  106880     // 512 floats
#define ZS_OFF   108928
#define TS_OFF   109184
#define SS_OFF   109440
#define SM_TOT   109696

__global__ __launch_bounds__(TPB, 2) void mm_main(
    const float* __restrict__ z,
    float* __restrict__ wout,     // [N, M]
    float* __restrict__ zhat,     // [N, 256]
    int M, int NCH)
{
    extern __shared__ char smc[];
    const uint32_t sbase = smem_u32(smc);
    const uint32_t sA = sbase + A_OFF;
    uint32_t* rmax = (uint32_t*)(smc + RMAX_OFF);
    uint32_t* tenc = (uint32_t*)(smc + TENC_OFF);
    int*      flg  = (int*)(smc + FLG_OFF);
    float*    red  = (float*)(smc + RED_OFF);
    float*    Zs   = (float*)(smc + ZS_OFF);
    float*    Ts   = (float*)(smc + TS_OFF);
    float*    Ss   = (float*)(smc + SS_OFF);

    const int tid = threadIdx.x, wid = tid >> 5, lane = tid & 31;
    const int wr = wid >> 1, wc = wid & 1;
    const long long gr0 = (long long)blockIdx.x * RB;
    const int r0l = wr * 16 + (lane >> 2), r1l = r0l + 8;

    // ---- init rmax, build A tile ----
    for (int i = tid; i < NCH * 64; i += TPB) rmax[i] = 0u;
    #pragma unroll 1
    for (int i = 0; i < 8; i++) {
        int r = wid * 8 + i;
        const float4* zr = (const float4*)(z + (gr0 + r) * DD);
        float4 a = zr[lane * 2], b = zr[lane * 2 + 1];
        float ss = a.x*a.x + a.y*a.y + a.z*a.z + a.w*a.w
                 + b.x*b.x + b.y*b.y + b.z*b.z + b.w*b.w;
        #pragma unroll
        for (int o = 16; o; o >>= 1) ss += __shfl_xor_sync(0xffffffffu, ss, o);
        float inv = 1.f / (sqrtf(ss) + EPSN);
        uint4 u;
        u.x = bf2(a.x * inv, a.y * inv); u.y = bf2(a.z * inv, a.w * inv);
        u.z = bf2(b.x * inv, b.y * inv); u.w = bf2(b.z * inv, b.w * inv);
        *(uint4*)(smc + A_OFF + r * 512 + ((lane ^ (r & 7)) * 16)) = u;
    }
    __syncthreads();

    // ---- hoist A fragments to registers (pass 1 only) ----
    uint32_t Areg[64];
    {
        const uint32_t h = lane >> 4;
        const uint32_t arow = wr * 16 + (lane & 15);
        const uint32_t abase = sA + arow * 512;
        const uint32_t arx = arow & 7;
        #pragma unroll
        for (int kk = 0; kk < 16; kk++) {
            uint32_t ca = ((uint32_t)(kk * 2 + h) ^ arx) << 4;
            LDSM4(Areg[4*kk], Areg[4*kk+1], Areg[4*kk+2], Areg[4*kk+3], abase + ca);
        }
    }

    // ================= PASS 1: GEMM1; Z; per-(row,chunk) max; overlapped zero-fill ======
    // pads of g_mn are exact zeros -> sim == 0.0 -> fexp == 1.0 exactly; corrected in
    // the Z reduction below. rmax picking up 0 from pads only ever over-flags (safe).
    float z0 = 0.f, z1 = 0.f;
    copyB(sbase + B1A_OFF, g_mn); CPCOMMIT();
    for (int ch = 0; ch < NCH; ch++) {
        CPWAIT(0);
        __syncthreads();   // publishes copy(ch); proves gemm(ch-1) drained other buffer
        if (ch + 1 < NCH) {
            copyB(sbase + (((ch + 1) & 1) ? B1B_OFF : B1A_OFF),
                  g_mn + (size_t)(ch + 1) * CH * DD);
            CPCOMMIT();
        }
        float acc[16] = {};
        gemm1_reg(Areg, sbase + ((ch & 1) ? B1B_OFF : B1A_OFF), wc, lane, acc);
        float m0 = acc[0], m1 = acc[2];
        #pragma unroll
        for (int nt = 0; nt < 4; nt++) {
            z0 += fexp(acc[nt * 4 + 0]) + fexp(acc[nt * 4 + 1]);
            z1 += fexp(acc[nt * 4 + 2]) + fexp(acc[nt * 4 + 3]);
            m0 = fmaxf(m0, fmaxf(acc[nt * 4 + 0], acc[nt * 4 + 1]));
            m1 = fmaxf(m1, fmaxf(acc[nt * 4 + 2], acc[nt * 4 + 3]));
        }
        atomicMax(&rmax[ch * 64 + r0l], encf(m0));
        atomicMax(&rmax[ch * 64 + r1l], encf(m1));
        // overlapped unconditional zero-fill of this chunk's w_hat region
        #pragma unroll
        for (int k = 0; k < 4; k++) {
            int idx = tid + k * 256;
            int r = idx >> 4, c4 = ch * CH + (idx & 15) * 4;
            if (c4 < M)   // M % 4 == 0
                *(float4*)(wout + (gr0 + r) * (long long)M + c4) =
                    make_float4(0.f, 0.f, 0.f, 0.f);
        }
    }
    __syncthreads();
    red[r0l * 8 + wc * 4 + (lane & 3)] = z0;
    red[r1l * 8 + wc * 4 + (lane & 3)] = z1;
    __syncthreads();
    const float padc = (float)(NCH * CH - M);
    if (tid < 64) {
        float s = 0.f;
        #pragma unroll
        for (int j = 0; j < 8; j++) s += red[tid * 8 + j];
        s -= padc;                           // remove exact pad contribution
        Zs[tid] = 1.0f / s;
        float T = logf(LAMBF * s) - 1e-3f;   // conservative skip threshold
        Ts[tid] = T;
        tenc[tid] = encf(T);
    }
    __syncthreads();
    // chunk flags
    if (tid < NCH) {
        int f = 0;
        #pragma unroll 4
        for (int r = 0; r < 64; r++) f |= (rmax[tid * 64 + r] > tenc[r]);
        flg[tid] = f;
    }
    __syncthreads();

    // ================= PHASE A (rare): flagged chunks =================
    const float invZ0 = Zs[r0l], invZ1 = Zs[r1l];
    const float T0 = Ts[r0l],    T1 = Ts[r1l];
    float s0 = 0.f, s1 = 0.f;
    float zac[64] = {};
    int any = 0;
    for (int ch = 0; ch < NCH; ch++) {
        if (!flg[ch]) continue;
        any = 1;
        copyB(sbase + B1A_OFF, g_mn + (size_t)ch * CH * DD);
        CPCOMMIT(); CPWAIT(0);
        __syncthreads();
        float acc[16] = {};
        gemm1(sA, sbase + B1A_OFF, wr, wc, lane, acc);
        float* w0 = wout + (gr0 + r0l) * (long long)M;
        float* w1 = wout + (gr0 + r1l) * (long long)M;
        #pragma unroll
        for (int nt = 0; nt < 4; nt++) {
            int cl  = wc * 32 + nt * 8 + 2 * (lane & 3);
            int col = ch * CH + cl;
            float h00 = 0.f, h01 = 0.f, h10 = 0.f, h11 = 0.f;
            if (col < M) {
                float a0 = acc[nt*4+0], a1 = acc[nt*4+1], a2 = acc[nt*4+2], a3 = acc[nt*4+3];
                if (a0 > T0) h00 = shrinkf(fexp(a0) * invZ0);
                if (a1 > T0) h01 = shrinkf(fexp(a1) * invZ0);
                if (a2 > T1) h10 = shrinkf(fexp(a2) * invZ1);
                if (a3 > T1) h11 = shrinkf(fexp(a3) * invZ1);
                s0 += h00 + h01; s1 += h10 + h11;
                *(float2*)(w0 + col) = make_float2(h00, h01);   // unnormalized; fixed up later
                *(float2*)(w1 + col) = make_float2(h10, h11);
            }
            *(uint32_t*)(smc + P_OFF + r0l * 128 + (((cl >> 3) ^ (r0l & 7)) << 4) + (cl & 7) * 2)
                = bf2(h00, h01);
            *(uint32_t*)(smc + P_OFF + r1l * 128 + (((cl >> 3) ^ (r1l & 7)) << 4) + (cl & 7) * 2)
                = bf2(h10, h11);
        }
        __syncthreads();
        copyB(sbase + B1B_OFF, g_mt + (size_t)ch * CH * DD);
        CPCOMMIT(); CPWAIT(0);
        __syncthreads();
        gemm2(sbase + P_OFF, sbase + B1B_OFF, wr, wc, lane, zac);
        __syncthreads();
    }

    // ---- S reduction ----
    red[r0l * 8 + wc * 4 + (lane & 3)] = s0;
    red[r1l * 8 + wc * 4 + (lane & 3)] = s1;
    __syncthreads();
    if (tid < 64) {
        float s = 0.f;
        #pragma unroll
        for (int j = 0; j < 8; j++) s += red[tid * 8 + j];
        Ss[tid] = 1.0f / (s + EPSS);
    }
    __syncthreads();

    // ---- fixup flagged chunks: w_hat *= invS ----
    if (any) {
        for (int ch = 0; ch < NCH; ch++) {
            if (!flg[ch]) continue;
            for (int idx = tid; idx < 64 * 16; idx += TPB) {
                int r = idx >> 4;
                int c4 = ch * CH + (idx & 15) * 4;
                if (c4 < M) {
                    float4* p = (float4*)(wout + (gr0 + r) * (long long)M + c4);
                    float4 v = *p; float s = Ss[r];
                    v.x *= s; v.y *= s; v.z *= s; v.w *= s;
                    *p = v;
                }
            }
        }
        __syncthreads();
    }

    // ---- z_hat epilogue ----
    {
        const float invS0 = Ss[r0l], invS1 = Ss[r1l];
        float* zr0 = zhat + (gr0 + r0l) * DD;
        float* zr1 = zhat + (gr0 + r1l) * DD;
        #pragma unroll
        for (int g = 0; g < 8; g++) {
            #pragma unroll
            for (int t = 0; t < 2; t++) {
                int d = wc * 128 + g * 16 + t * 8 + 2 * (lane & 3);
                int ii = (g * 2 + t) * 4;
                *(float2*)(zr0 + d) = make_float2(zac[ii + 0] * invS0, zac[ii + 1] * invS0);
                *(float2*)(zr1 + d) = make_float2(zac[ii + 2] * invS1, zac[ii + 3] * invS1);
            }
        }
    }
}

// ---------------- host ----------------
extern "C" void kernel_launch(void* const* d_in, const int* in_sizes, int n_in,
                              void* d_out, int out_size) {
    const float* z   = (const float*)d_in[0];
    const float* mem = (const float*)d_in[1];
    const int N = in_sizes[0] / DD;
    const int M = in_sizes[1] / DD;
    const int NCH = (M + CH - 1) / CH;

    float* zhat = (float*)d_out;                 // [N, 256]
    float* wout = zhat + (size_t)N * DD;         // [N, M]

    cudaFuncSetAttribute(mm_main, cudaFuncAttributeMaxDynamicSharedMemorySize, SM_TOT);

    mm_prep<<<NCH * CH, 256>>>(mem, M);
    mm_main<<<N / RB, TPB, SM_TOT>>>(z, wout, zhat, M, NCH);
}

// round 9
// speedup vs baseline: 24.5221x; 1.1107x over previous
#include <cuda_runtime.h>
#include <cuda_bf16.h>
#include <math.h>
#include <stdint.h>

#define DD    256
#define RB    64          // z rows per CTA
#define CH    64          // memory cols per chunk
#define TPB   256
#define LAMBF 0.002f
#define EPSN  1e-10f
#define EPSS  1e-12f
#define MAXM  2048
#define NCHMX 32

// pre-swizzled bf16 operand tiles (scratch via __device__ globals)
__device__ __align__(16) __nv_bfloat16 g_mn[MAXM * DD];   // m_norm rows, ldmatrix swizzle
__device__ __align__(16) __nv_bfloat16 g_mt[MAXM * DD];   // mem^T chunk-blocked, ldmatrix swizzle

// ---------------- helpers ----------------
__device__ __forceinline__ uint32_t smem_u32(const void* p) {
    uint32_t a;
    asm("{ .reg .u64 t; cvta.to.shared.u64 t, %1; cvt.u32.u64 %0, t; }" : "=r"(a) : "l"(p));
    return a;
}

#define LDSM4(r0, r1, r2, r3, a) \
    asm volatile("ldmatrix.sync.aligned.m8n8.x4.shared.b16 {%0,%1,%2,%3}, [%4];" \
                 : "=r"(r0), "=r"(r1), "=r"(r2), "=r"(r3) : "r"(a))

#define MMA16816(d, A, b0, b1) \
    asm volatile("mma.sync.aligned.m16n8k16.row.col.f32.bf16.bf16.f32 " \
                 "{%0,%1,%2,%3},{%4,%5,%6,%7},{%8,%9},{%0,%1,%2,%3};" \
                 : "+f"((d)[0]), "+f"((d)[1]), "+f"((d)[2]), "+f"((d)[3]) \
                 : "r"((A)[0]), "r"((A)[1]), "r"((A)[2]), "r"((A)[3]), "r"(b0), "r"(b1))

#define CPASYNC16(dst, src) \
    asm volatile("cp.async.cg.shared.global [%0], [%1], 16;" :: "r"(dst), "l"(src) : "memory")
#define CPCOMMIT() asm volatile("cp.async.commit_group;" ::: "memory")
#define CPWAIT(n)  asm volatile("cp.async.wait_group %0;" :: "n"(n) : "memory")

__device__ __forceinline__ uint32_t bf2(float lo, float hi) {
    uint32_t r;
    asm("cvt.rn.bf16x2.f32 %0, %1, %2;" : "=r"(r) : "f"(hi), "f"(lo));
    return r;
}

// order-preserving float->uint encode (for atomicMax on signed floats)
__device__ __forceinline__ uint32_t encf(float x) {
    uint32_t u = __float_as_uint(x);
    return (u & 0x80000000u) ? ~u : (u | 0x80000000u);
}

// fast exp via MUFU: exp(x) = 2^(x*log2e). rel err ~1e-7; ex2(0) == 1.0f exactly.
// 2 instructions vs 11 for the polynomial — fexp was ~28% of all issued instr.
__device__ __forceinline__ float fexp(float x) {
    float r;
    asm("ex2.approx.f32 %0, %1;" : "=f"(r) : "f"(x * 1.4426950408889634f));
    return r;
}

__device__ __forceinline__ float shrinkf(float w) {
    float d = w - LAMBF;
    return fmaxf(d, 0.f) * w / (fabsf(d) + EPSS);
}

// ---------------- prologue: normalize memory + build swizzled operand tiles ----------------
__global__ void mm_prep(const float* __restrict__ mem, int M) {
    int m = blockIdx.x;
    int d = threadIdx.x;
    float v = (m < M) ? mem[(size_t)m * DD + d] : 0.f;
    float ss = v * v;
    #pragma unroll
    for (int o = 16; o; o >>= 1) ss += __shfl_xor_sync(0xffffffffu, ss, o);
    __shared__ float ws[8];
    __shared__ float sc;
    if ((d & 31) == 0) ws[d >> 5] = ss;
    __syncthreads();
    if (d == 0) {
        float t = 0.f;
        #pragma unroll
        for (int i = 0; i < 8; i++) t += ws[i];
        sc = sqrtf(t) + EPSN;
    }
    __syncthreads();
    g_mn[m * 256 + (((d >> 3) ^ (m & 7)) * 8) + (d & 7)] = __float2bfloat16(v / sc);
    int ch = m >> 6, c = m & 63;
    g_mt[ch * 16384 + d * 64 + (((c >> 3) ^ (d & 7)) * 8) + (c & 7)] = __float2bfloat16(v);
}

// ---------------- GEMM micro-kernels ----------------
__device__ __forceinline__ void gemm1_reg(const uint32_t* Areg, uint32_t sB, int wc, int lane,
                                          float acc[16]) {
    const uint32_t h = lane >> 4;
    const uint32_t brow = wc * 32 + (lane & 15);
    const uint32_t bbase = sB + brow * 512;
    const uint32_t brx = brow & 7;
    #pragma unroll
    for (int kk = 0; kk < 16; kk++) {
        uint32_t cb = ((uint32_t)(kk * 2 + h) ^ brx) << 4;
        uint32_t p0, p1, p2, p3, q0, q1, q2, q3;
        LDSM4(p0, p1, p2, p3, bbase + cb);
        LDSM4(q0, q1, q2, q3, bbase + 16 * 512 + cb);
        MMA16816(acc + 0,  (Areg + 4 * kk), p0, p2);
        MMA16816(acc + 4,  (Areg + 4 * kk), p1, p3);
        MMA16816(acc + 8,  (Areg + 4 * kk), q0, q2);
        MMA16816(acc + 12, (Areg + 4 * kk), q1, q3);
    }
}

__device__ __forceinline__ void gemm1(uint32_t sA, uint32_t sB, int wr, int wc, int lane,
                                      float acc[16]) {
    const uint32_t h = lane >> 4;
    const uint32_t arow = wr * 16 + (lane & 15);
    const uint32_t abase = sA + arow * 512;
    const uint32_t arx = arow & 7;
    const uint32_t brow = wc * 32 + (lane & 15);
    const uint32_t bbase = sB + brow * 512;
    const uint32_t brx = brow & 7;
    #pragma unroll
    for (int kk = 0; kk < 16; kk++) {
        uint32_t ca = ((uint32_t)(kk * 2 + h) ^ arx) << 4;
        uint32_t cb = ((uint32_t)(kk * 2 + h) ^ brx) << 4;
        uint32_t A[4], p0, p1, p2, p3, q0, q1, q2, q3;
        LDSM4(A[0], A[1], A[2], A[3], abase + ca);
        LDSM4(p0, p1, p2, p3, bbase + cb);
        LDSM4(q0, q1, q2, q3, bbase + 16 * 512 + cb);
        MMA16816(acc + 0,  A, p0, p2);
        MMA16816(acc + 4,  A, p1, p3);
        MMA16816(acc + 8,  A, q0, q2);
        MMA16816(acc + 12, A, q1, q3);
    }
}

__device__ __forceinline__ void gemm2(uint32_t sP, uint32_t sB2, int wr, int wc, int lane,
                                      float zac[64]) {
    const uint32_t h = lane >> 4;
    const uint32_t prow = wr * 16 + (lane & 15);
    const uint32_t pbase = sP + prow * 128;
    const uint32_t prx = prow & 7;
    const uint32_t drow = wc * 128 + (lane & 15);
    const uint32_t dbase = sB2 + drow * 128;
    const uint32_t drx = drow & 7;
    #pragma unroll
    for (int kk = 0; kk < 4; kk++) {
        uint32_t ca = ((uint32_t)(kk * 2 + h) ^ prx) << 4;
        uint32_t cb = ((uint32_t)(kk * 2 + h) ^ drx) << 4;
        uint32_t A[4];
        LDSM4(A[0], A[1], A[2], A[3], pbase + ca);
        #pragma unroll
        for (int g = 0; g < 8; g++) {
            uint32_t b0, b1, b2, b3;
            LDSM4(b0, b1, b2, b3, dbase + g * 2048 + cb);
            MMA16816(zac + (g * 2) * 4,     A, b0, b2);
            MMA16816(zac + (g * 2 + 1) * 4, A, b1, b3);
        }
    }
}

__device__ __forceinline__ void copyB(uint32_t sdst, const __nv_bfloat16* g) {
    const char* gp = (const char*)g;
    #pragma unroll
    for (int k = 0; k < 8; k++) {
        int idx = threadIdx.x + k * 256;
        CPASYNC16(sdst + idx * 16, gp + (size_t)idx * 16);
    }
}

// smem offsets (bytes)
#define A_OFF    0          // A tile, resident through phase A (32K)
#define B1A_OFF  32768      // pass1 B dbl / phase A B1 tile
#define B1B_OFF  65536      // pass1 B dbl / phase A memT tile
#define RMAX_OFF 98304      // 32 chunks x 64 rows x 4B = 8K; phase A: P tile
#define P_OFF    98304
#define TENC_OFF 106496     // 64 x 4B
#define FLG_OFF  106752     // 32 x 4B
#define RED_OFF  106880     // 512 floats
#define ZS_OFF   108928
#define TS_OFF   109184
#define SS_OFF   109440
#define SM_TOT   109696

__global__ __launch_bounds__(TPB, 2) void mm_main(
    const float* __restrict__ z,
    float* __restrict__ wout,     // [N, M]
    float* __restrict__ zhat,     // [N, 256]
    int M, int NCH)
{
    extern __shared__ char smc[];
    const uint32_t sbase = smem_u32(smc);
    const uint32_t sA = sbase + A_OFF;
    uint32_t* rmax = (uint32_t*)(smc + RMAX_OFF);
    uint32_t* tenc = (uint32_t*)(smc + TENC_OFF);
    int*      flg  = (int*)(smc + FLG_OFF);
    float*    red  = (float*)(smc + RED_OFF);
    float*    Zs   = (float*)(smc + ZS_OFF);
    float*    Ts   = (float*)(smc + TS_OFF);
    float*    Ss   = (float*)(smc + SS_OFF);

    const int tid = threadIdx.x, wid = tid >> 5, lane = tid & 31;
    const int wr = wid >> 1, wc = wid & 1;
    const long long gr0 = (long long)blockIdx.x * RB;
    const int r0l = wr * 16 + (lane >> 2), r1l = r0l + 8;

    // ---- init rmax, build A tile ----
    for (int i = tid; i < NCH * 64; i += TPB) rmax[i] = 0u;
    #pragma unroll 1
    for (int i = 0; i < 8; i++) {
        int r = wid * 8 + i;
        const float4* zr = (const float4*)(z + (gr0 + r) * DD);
        float4 a = zr[lane * 2], b = zr[lane * 2 + 1];
        float ss = a.x*a.x + a.y*a.y + a.z*a.z + a.w*a.w
                 + b.x*b.x + b.y*b.y + b.z*b.z + b.w*b.w;
        #pragma unroll
        for (int o = 16; o; o >>= 1) ss += __shfl_xor_sync(0xffffffffu, ss, o);
        float inv = 1.f / (sqrtf(ss) + EPSN);
        uint4 u;
        u.x = bf2(a.x * inv, a.y * inv); u.y = bf2(a.z * inv, a.w * inv);
        u.z = bf2(b.x * inv, b.y * inv); u.w = bf2(b.z * inv, b.w * inv);
        *(uint4*)(smc + A_OFF + r * 512 + ((lane ^ (r & 7)) * 16)) = u;
    }
    __syncthreads();

    // ---- hoist A fragments to registers (pass 1 only) ----
    uint32_t Areg[64];
    {
        const uint32_t h = lane >> 4;
        const uint32_t arow = wr * 16 + (lane & 15);
        const uint32_t abase = sA + arow * 512;
        const uint32_t arx = arow & 7;
        #pragma unroll
        for (int kk = 0; kk < 16; kk++) {
            uint32_t ca = ((uint32_t)(kk * 2 + h) ^ arx) << 4;
            LDSM4(Areg[4*kk], Areg[4*kk+1], Areg[4*kk+2], Areg[4*kk+3], abase + ca);
        }
    }

    // ================= PASS 1: GEMM1; Z; per-(row,chunk) max; overlapped zero-fill ======
    float z0 = 0.f, z1 = 0.f;
    copyB(sbase + B1A_OFF, g_mn); CPCOMMIT();
    for (int ch = 0; ch < NCH; ch++) {
        CPWAIT(0);
        __syncthreads();   // publishes copy(ch); proves gemm(ch-1) drained other buffer
        if (ch + 1 < NCH) {
            copyB(sbase + (((ch + 1) & 1) ? B1B_OFF : B1A_OFF),
                  g_mn + (size_t)(ch + 1) * CH * DD);
            CPCOMMIT();
        }
        float acc[16] = {};
        gemm1_reg(Areg, sbase + ((ch & 1) ? B1B_OFF : B1A_OFF), wc, lane, acc);
        float m0 = acc[0], m1 = acc[2];
        #pragma unroll
        for (int nt = 0; nt < 4; nt++) {
            z0 += fexp(acc[nt * 4 + 0]) + fexp(acc[nt * 4 + 1]);
            z1 += fexp(acc[nt * 4 + 2]) + fexp(acc[nt * 4 + 3]);
            m0 = fmaxf(m0, fmaxf(acc[nt * 4 + 0], acc[nt * 4 + 1]));
            m1 = fmaxf(m1, fmaxf(acc[nt * 4 + 2], acc[nt * 4 + 3]));
        }
        // quad reduction first (lanes 0-3 of each quad share the row), then 1 atomic
        m0 = fmaxf(m0, __shfl_xor_sync(0xffffffffu, m0, 1));
        m0 = fmaxf(m0, __shfl_xor_sync(0xffffffffu, m0, 2));
        m1 = fmaxf(m1, __shfl_xor_sync(0xffffffffu, m1, 1));
        m1 = fmaxf(m1, __shfl_xor_sync(0xffffffffu, m1, 2));
        if ((lane & 3) == 0) {
            atomicMax(&rmax[ch * 64 + r0l], encf(m0));
            atomicMax(&rmax[ch * 64 + r1l], encf(m1));
        }
        // overlapped unconditional zero-fill of this chunk's w_hat region
        #pragma unroll
        for (int k = 0; k < 4; k++) {
            int idx = tid + k * 256;
            int r = idx >> 4, c4 = ch * CH + (idx & 15) * 4;
            if (c4 < M)   // M % 4 == 0
                *(float4*)(wout + (gr0 + r) * (long long)M + c4) =
                    make_float4(0.f, 0.f, 0.f, 0.f);
        }
    }
    __syncthreads();
    red[r0l * 8 + wc * 4 + (lane & 3)] = z0;
    red[r1l * 8 + wc * 4 + (lane & 3)] = z1;
    __syncthreads();
    const float padc = (float)(NCH * CH - M);
    if (tid < 64) {
        float s = 0.f;
        #pragma unroll
        for (int j = 0; j < 8; j++) s += red[tid * 8 + j];
        s -= padc;                           // remove exact pad contribution (fexp(0)==1)
        Zs[tid] = 1.0f / s;
        float T = logf(LAMBF * s) - 1e-3f;   // conservative skip threshold
        Ts[tid] = T;
        tenc[tid] = encf(T);
    }
    __syncthreads();
    // chunk flags
    if (tid < NCH) {
        int f = 0;
        #pragma unroll 4
        for (int r = 0; r < 64; r++) f |= (rmax[tid * 64 + r] > tenc[r]);
        flg[tid] = f;
    }
    __syncthreads();

    // ================= PHASE A (rare): flagged chunks =================
    const float invZ0 = Zs[r0l], invZ1 = Zs[r1l];
    const float T0 = Ts[r0l],    T1 = Ts[r1l];
    float s0 = 0.f, s1 = 0.f;
    float zac[64] = {};
    int any = 0;
    for (int ch = 0; ch < NCH; ch++) {
        if (!flg[ch]) continue;
        any = 1;
        copyB(sbase + B1A_OFF, g_mn + (size_t)ch * CH * DD);
        CPCOMMIT(); CPWAIT(0);
        __syncthreads();
        float acc[16] = {};
        gemm1(sA, sbase + B1A_OFF, wr, wc, lane, acc);
        float* w0 = wout + (gr0 + r0l) * (long long)M;
        float* w1 = wout + (gr0 + r1l) * (long long)M;
        #pragma unroll
        for (int nt = 0; nt < 4; nt++) {
            int cl  = wc * 32 + nt * 8 + 2 * (lane & 3);
            int col = ch * CH + cl;
            float h00 = 0.f, h01 = 0.f, h10 = 0.f, h11 = 0.f;
            if (col < M) {
                float a0 = acc[nt*4+0], a1 = acc[nt*4+1], a2 = acc[nt*4+2], a3 = acc[nt*4+3];
                if (a0 > T0) h00 = shrinkf(fexp(a0) * invZ0);
                if (a1 > T0) h01 = shrinkf(fexp(a1) * invZ0);
                if (a2 > T1) h10 = shrinkf(fexp(a2) * invZ1);
                if (a3 > T1) h11 = shrinkf(fexp(a3) * invZ1);
                s0 += h00 + h01; s1 += h10 + h11;
                *(float2*)(w0 + col) = make_float2(h00, h01);   // unnormalized; fixed up later
                *(float2*)(w1 + col) = make_float2(h10, h11);
            }
            *(uint32_t*)(smc + P_OFF + r0l * 128 + (((cl >> 3) ^ (r0l & 7)) << 4) + (cl & 7) * 2)
                = bf2(h00, h01);
            *(uint32_t*)(smc + P_OFF + r1l * 128 + (((cl >> 3) ^ (r1l & 7)) << 4) + (cl & 7) * 2)
                = bf2(h10, h11);
        }
        __syncthreads();
        copyB(sbase + B1B_OFF, g_mt + (size_t)ch * CH * DD);
        CPCOMMIT(); CPWAIT(0);
        __syncthreads();
        gemm2(sbase + P_OFF, sbase + B1B_OFF, wr, wc, lane, zac);
        __syncthreads();
    }

    // ---- S reduction ----
    red[r0l * 8 + wc * 4 + (lane & 3)] = s0;
    red[r1l * 8 + wc * 4 + (lane & 3)] = s1;
    __syncthreads();
    if (tid < 64) {
        float s = 0.f;
        #pragma unroll
        for (int j = 0; j < 8; j++) s += red[tid * 8 + j];
        Ss[tid] = 1.0f / (s + EPSS);
    }
    __syncthreads();

    // ---- fixup flagged chunks: w_hat *= invS ----
    if (any) {
        for (int ch = 0; ch < NCH; ch++) {
            if (!flg[ch]) continue;
            for (int idx = tid; idx < 64 * 16; idx += TPB) {
                int r = idx >> 4;
                int c4 = ch * CH + (idx & 15) * 4;
                if (c4 < M) {
                    float4* p = (float4*)(wout + (gr0 + r) * (long long)M + c4);
                    float4 v = *p; float s = Ss[r];
                    v.x *= s; v.y *= s; v.z *= s; v.w *= s;
                    *p = v;
                }
            }
        }
        __syncthreads();
    }

    // ---- z_hat epilogue ----
    {
        const float invS0 = Ss[r0l], invS1 = Ss[r1l];
        float* zr0 = zhat + (gr0 + r0l) * DD;
        float* zr1 = zhat + (gr0 + r1l) * DD;
        #pragma unroll
        for (int g = 0; g < 8; g++) {
            #pragma unroll
            for (int t = 0; t < 2; t++) {
                int d = wc * 128 + g * 16 + t * 8 + 2 * (lane & 3);
                int ii = (g * 2 + t) * 4;
                *(float2*)(zr0 + d) = make_float2(zac[ii + 0] * invS0, zac[ii + 1] * invS0);
                *(float2*)(zr1 + d) = make_float2(zac[ii + 2] * invS1, zac[ii + 3] * invS1);
            }
        }
    }
}

// ---------------- host ----------------
extern "C" void kernel_launch(void* const* d_in, const int* in_sizes, int n_in,
                              void* d_out, int out_size) {
    const float* z   = (const float*)d_in[0];
    const float* mem = (const float*)d_in[1];
    const int N = in_sizes[0] / DD;
    const int M = in_sizes[1] / DD;
    const int NCH = (M + CH - 1) / CH;

    float* zhat = (float*)d_out;                 // [N, 256]
    float* wout = zhat + (size_t)N * DD;         // [N, M]

    cudaFuncSetAttribute(mm_main, cudaFuncAttributeMaxDynamicSharedMemorySize, SM_TOT);

    mm_prep<<<NCH * CH, 256>>>(mem, M);
    mm_main<<<N / RB, TPB, SM_TOT>>>(z, wout, zhat, M, NCH);
}

// round 10
// speedup vs baseline: 25.8846x; 1.0556x over previous
#include <cuda_runtime.h>
#include <cuda_bf16.h>
#include <math.h>
#include <stdint.h>

#define DD    256
#define RB    64          // z rows per CTA
#define CH    64          // memory cols per chunk
#define TPB   256
#define LAMBF 0.002f
#define EPSN  1e-10f
#define EPSS  1e-12f
#define MAXM  2048
#define NCHMX 32

// pre-swizzled bf16 operand tiles (scratch via __device__ globals)
__device__ __align__(16) __nv_bfloat16 g_mn[MAXM * DD];   // m_norm rows, ldmatrix swizzle
__device__ __align__(16) __nv_bfloat16 g_mt[MAXM * DD];   // mem^T chunk-blocked, ldmatrix swizzle

// ---------------- helpers ----------------
__device__ __forceinline__ uint32_t smem_u32(const void* p) {
    uint32_t a;
    asm("{ .reg .u64 t; cvta.to.shared.u64 t, %1; cvt.u32.u64 %0, t; }" : "=r"(a) : "l"(p));
    return a;
}

#define LDSM4(r0, r1, r2, r3, a) \
    asm volatile("ldmatrix.sync.aligned.m8n8.x4.shared.b16 {%0,%1,%2,%3}, [%4];" \
                 : "=r"(r0), "=r"(r1), "=r"(r2), "=r"(r3) : "r"(a))

#define MMA16816(d, A, b0, b1) \
    asm volatile("mma.sync.aligned.m16n8k16.row.col.f32.bf16.bf16.f32 " \
                 "{%0,%1,%2,%3},{%4,%5,%6,%7},{%8,%9},{%0,%1,%2,%3};" \
                 : "+f"((d)[0]), "+f"((d)[1]), "+f"((d)[2]), "+f"((d)[3]) \
                 : "r"((A)[0]), "r"((A)[1]), "r"((A)[2]), "r"((A)[3]), "r"(b0), "r"(b1))

#define CPASYNC16(dst, src) \
    asm volatile("cp.async.cg.shared.global [%0], [%1], 16;" :: "r"(dst), "l"(src) : "memory")
#define CPCOMMIT() asm volatile("cp.async.commit_group;" ::: "memory")
#define CPWAIT(n)  asm volatile("cp.async.wait_group %0;" :: "n"(n) : "memory")

__device__ __forceinline__ uint32_t bf2(float lo, float hi) {
    uint32_t r;
    asm("cvt.rn.bf16x2.f32 %0, %1, %2;" : "=r"(r) : "f"(hi), "f"(lo));
    return r;
}

// order-preserving float->uint encode (for atomicMax on signed floats)
__device__ __forceinline__ uint32_t encf(float x) {
    uint32_t u = __float_as_uint(x);
    return (u & 0x80000000u) ? ~u : (u | 0x80000000u);
}

// fast exp via MUFU: exp(x) = 2^(x*log2e). rel err ~1e-7; ex2(0) == 1.0f exactly.
__device__ __forceinline__ float fexp(float x) {
    float r;
    asm("ex2.approx.f32 %0, %1;" : "=f"(r) : "f"(x * 1.4426950408889634f));
    return r;
}

__device__ __forceinline__ float shrinkf(float w) {
    float d = w - LAMBF;
    return fmaxf(d, 0.f) * w / (fabsf(d) + EPSS);
}

// ---------------- prologue: normalize memory + build swizzled operand tiles ----------------
__global__ void mm_prep(const float* __restrict__ mem, int M) {
    int m = blockIdx.x;
    int d = threadIdx.x;
    float v = (m < M) ? mem[(size_t)m * DD + d] : 0.f;
    float ss = v * v;
    #pragma unroll
    for (int o = 16; o; o >>= 1) ss += __shfl_xor_sync(0xffffffffu, ss, o);
    __shared__ float ws[8];
    __shared__ float sc;
    if ((d & 31) == 0) ws[d >> 5] = ss;
    __syncthreads();
    if (d == 0) {
        float t = 0.f;
        #pragma unroll
        for (int i = 0; i < 8; i++) t += ws[i];
        sc = sqrtf(t) + EPSN;
    }
    __syncthreads();
    g_mn[m * 256 + (((d >> 3) ^ (m & 7)) * 8) + (d & 7)] = __float2bfloat16(v / sc);
    int ch = m >> 6, c = m & 63;
    g_mt[ch * 16384 + d * 64 + (((c >> 3) ^ (d & 7)) * 8) + (c & 7)] = __float2bfloat16(v);
}

// ---------------- GEMM micro-kernels ----------------
// pass-1: A register-resident, B software-pipelined p/q rotation:
//   LDSM q(kk) -> MMA p(kk) -> LDSM p(kk+1) -> MMA q(kk)
// every LDSM issues >=2 MMA-slots ahead of its consumer; zero extra registers.
__device__ __forceinline__ void gemm1_reg(const uint32_t* Areg, uint32_t sB, int wc, int lane,
                                          float acc[16]) {
    const uint32_t h = lane >> 4;
    const uint32_t brow = wc * 32 + (lane & 15);
    const uint32_t bbase = sB + brow * 512;
    const uint32_t brx = brow & 7;
    uint32_t p[4], q[4];
    LDSM4(p[0], p[1], p[2], p[3], bbase + ((h ^ brx) << 4));
    #pragma unroll
    for (int kk = 0; kk < 16; kk++) {
        uint32_t cb = ((uint32_t)(kk * 2 + h) ^ brx) << 4;
        LDSM4(q[0], q[1], q[2], q[3], bbase + 16 * 512 + cb);
        MMA16816(acc + 0, (Areg + 4 * kk), p[0], p[2]);
        MMA16816(acc + 4, (Areg + 4 * kk), p[1], p[3]);
        if (kk < 15) {
            uint32_t cbn = ((uint32_t)((kk + 1) * 2 + h) ^ brx) << 4;
            LDSM4(p[0], p[1], p[2], p[3], bbase + cbn);
        }
        MMA16816(acc + 8,  (Areg + 4 * kk), q[0], q[2]);
        MMA16816(acc + 12, (Areg + 4 * kk), q[1], q[3]);
    }
}

__device__ __forceinline__ void gemm1(uint32_t sA, uint32_t sB, int wr, int wc, int lane,
                                      float acc[16]) {
    const uint32_t h = lane >> 4;
    const uint32_t arow = wr * 16 + (lane & 15);
    const uint32_t abase = sA + arow * 512;
    const uint32_t arx = arow & 7;
    const uint32_t brow = wc * 32 + (lane & 15);
    const uint32_t bbase = sB + brow * 512;
    const uint32_t brx = brow & 7;
    #pragma unroll
    for (int kk = 0; kk < 16; kk++) {
        uint32_t ca = ((uint32_t)(kk * 2 + h) ^ arx) << 4;
        uint32_t cb = ((uint32_t)(kk * 2 + h) ^ brx) << 4;
        uint32_t A[4], p0, p1, p2, p3, q0, q1, q2, q3;
        LDSM4(A[0], A[1], A[2], A[3], abase + ca);
        LDSM4(p0, p1, p2, p3, bbase + cb);
        LDSM4(q0, q1, q2, q3, bbase + 16 * 512 + cb);
        MMA16816(acc + 0,  A, p0, p2);
        MMA16816(acc + 4,  A, p1, p3);
        MMA16816(acc + 8,  A, q0, q2);
        MMA16816(acc + 12, A, q1, q3);
    }
}

__device__ __forceinline__ void gemm2(uint32_t sP, uint32_t sB2, int wr, int wc, int lane,
                                      float zac[64]) {
    const uint32_t h = lane >> 4;
    const uint32_t prow = wr * 16 + (lane & 15);
    const uint32_t pbase = sP + prow * 128;
    const uint32_t prx = prow & 7;
    const uint32_t drow = wc * 128 + (lane & 15);
    const uint32_t dbase = sB2 + drow * 128;
    const uint32_t drx = drow & 7;
    #pragma unroll
    for (int kk = 0; kk < 4; kk++) {
        uint32_t ca = ((uint32_t)(kk * 2 + h) ^ prx) << 4;
        uint32_t cb = ((uint32_t)(kk * 2 + h) ^ drx) << 4;
        uint32_t A[4];
        LDSM4(A[0], A[1], A[2], A[3], pbase + ca);
        #pragma unroll
        for (int g = 0; g < 8; g++) {
            uint32_t b0, b1, b2, b3;
            LDSM4(b0, b1, b2, b3, dbase + g * 2048 + cb);
            MMA16816(zac + (g * 2) * 4,     A, b0, b2);
            MMA16816(zac + (g * 2 + 1) * 4, A, b1, b3);
        }
    }
}

__device__ __forceinline__ void copyB(uint32_t sdst, const __nv_bfloat16* g) {
    const char* gp = (const char*)g;
    #pragma unroll
    for (int k = 0; k < 8; k++) {
        int idx = threadIdx.x + k * 256;
        CPASYNC16(sdst + idx * 16, gp + (size_t)idx * 16);
    }
}

// smem offsets (bytes)
#define A_OFF    0          // A tile, resident through phase A (32K)
#define B1A_OFF  32768      // pass1 B dbl / phase A B1 tile
#define B1B_OFF  65536      // pass1 B dbl / phase A memT tile
#define RMAX_OFF 98304      // 32 chunks x 64 rows x 4B = 8K; phase A: P tile
#define P_OFF    98304
#define TENC_OFF 106496     // 64 x 4B
#define FLG_OFF  106752     // 32 x 4B
#define RED_OFF  106880     // 512 floats
#define ZS_OFF   108928
#define TS_OFF   109184
#define SS_OFF   109440
#define SM_TOT   109696

__global__ __launch_bounds__(TPB, 2) void mm_main(
    const float* __restrict__ z,
    float* __restrict__ wout,     // [N, M]
    float* __restrict__ zhat,     // [N, 256]
    int M, int NCH)
{
    extern __shared__ char smc[];
    const uint32_t sbase = smem_u32(smc);
    const uint32_t sA = sbase + A_OFF;
    uint32_t* rmax = (uint32_t*)(smc + RMAX_OFF);
    uint32_t* tenc = (uint32_t*)(smc + TENC_OFF);
    int*      flg  = (int*)(smc + FLG_OFF);
    float*    red  = (float*)(smc + RED_OFF);
    float*    Zs   = (float*)(smc + ZS_OFF);
    float*    Ts   = (float*)(smc + TS_OFF);
    float*    Ss   = (float*)(smc + SS_OFF);

    const int tid = threadIdx.x, wid = tid >> 5, lane = tid & 31;
    const int wr = wid >> 1, wc = wid & 1;
    const long long gr0 = (long long)blockIdx.x * RB;
    const int r0l = wr * 16 + (lane >> 2), r1l = r0l + 8;

    // ---- init rmax, build A tile ----
    for (int i = tid; i < NCH * 64; i += TPB) rmax[i] = 0u;
    #pragma unroll 1
    for (int i = 0; i < 8; i++) {
        int r = wid * 8 + i;
        const float4* zr = (const float4*)(z + (gr0 + r) * DD);
        float4 a = zr[lane * 2], b = zr[lane * 2 + 1];
        float ss = a.x*a.x + a.y*a.y + a.z*a.z + a.w*a.w
                 + b.x*b.x + b.y*b.y + b.z*b.z + b.w*b.w;
        #pragma unroll
        for (int o = 16; o; o >>= 1) ss += __shfl_xor_sync(0xffffffffu, ss, o);
        float inv = 1.f / (sqrtf(ss) + EPSN);
        uint4 u;
        u.x = bf2(a.x * inv, a.y * inv); u.y = bf2(a.z * inv, a.w * inv);
        u.z = bf2(b.x * inv, b.y * inv); u.w = bf2(b.z * inv, b.w * inv);
        *(uint4*)(smc + A_OFF + r * 512 + ((lane ^ (r & 7)) * 16)) = u;
    }
    __syncthreads();

    // ---- hoist A fragments to registers (pass 1 only) ----
    uint32_t Areg[64];
    {
        const uint32_t h = lane >> 4;
        const uint32_t arow = wr * 16 + (lane & 15);
        const uint32_t abase = sA + arow * 512;
        const uint32_t arx = arow & 7;
        #pragma unroll
        for (int kk = 0; kk < 16; kk++) {
            uint32_t ca = ((uint32_t)(kk * 2 + h) ^ arx) << 4;
            LDSM4(Areg[4*kk], Areg[4*kk+1], Areg[4*kk+2], Areg[4*kk+3], abase + ca);
        }
    }

    // ---- hoisted zero-fill row pointers (advanced by CH per chunk) ----
    float4* fp[4];
    {
        int cb = (tid & 15) * 4;
        #pragma unroll
        for (int k = 0; k < 4; k++)
            fp[k] = (float4*)(wout + (gr0 + (tid >> 4) + k * 16) * (long long)M + cb);
    }
    const int cbase = (tid & 15) * 4;

    // ================= PASS 1: GEMM1; Z; per-(row,chunk) max; overlapped zero-fill ======
    float z0 = 0.f, z1 = 0.f;
    copyB(sbase + B1A_OFF, g_mn); CPCOMMIT();
    for (int ch = 0; ch < NCH; ch++) {
        CPWAIT(0);
        __syncthreads();   // publishes copy(ch); proves gemm(ch-1) drained other buffer
        if (ch + 1 < NCH) {
            copyB(sbase + (((ch + 1) & 1) ? B1B_OFF : B1A_OFF),
                  g_mn + (size_t)(ch + 1) * CH * DD);
            CPCOMMIT();
        }
        // zero-fill this chunk's w_hat region first: independent STGs issue
        // during gemm's LDSM warm-up instead of serializing after it
        if (ch * CH + cbase < M) {   // M % 4 == 0
            const float4 zero4 = make_float4(0.f, 0.f, 0.f, 0.f);
            #pragma unroll
            for (int k = 0; k < 4; k++) *fp[k] = zero4;
        }
        #pragma unroll
        for (int k = 0; k < 4; k++) fp[k] += CH / 4;
        float acc[16] = {};
        gemm1_reg(Areg, sbase + ((ch & 1) ? B1B_OFF : B1A_OFF), wc, lane, acc);
        float m0 = acc[0], m1 = acc[2];
        #pragma unroll
        for (int nt = 0; nt < 4; nt++) {
            z0 += fexp(acc[nt * 4 + 0]) + fexp(acc[nt * 4 + 1]);
            z1 += fexp(acc[nt * 4 + 2]) + fexp(acc[nt * 4 + 3]);
            m0 = fmaxf(m0, fmaxf(acc[nt * 4 + 0], acc[nt * 4 + 1]));
            m1 = fmaxf(m1, fmaxf(acc[nt * 4 + 2], acc[nt * 4 + 3]));
        }
        // quad reduction first, then 1 atomic per row
        m0 = fmaxf(m0, __shfl_xor_sync(0xffffffffu, m0, 1));
        m0 = fmaxf(m0, __shfl_xor_sync(0xffffffffu, m0, 2));
        m1 = fmaxf(m1, __shfl_xor_sync(0xffffffffu, m1, 1));
        m1 = fmaxf(m1, __shfl_xor_sync(0xffffffffu, m1, 2));
        if ((lane & 3) == 0) {
            atomicMax(&rmax[ch * 64 + r0l], encf(m0));
            atomicMax(&rmax[ch * 64 + r1l], encf(m1));
        }
    }
    __syncthreads();
    red[r0l * 8 + wc * 4 + (lane & 3)] = z0;
    red[r1l * 8 + wc * 4 + (lane & 3)] = z1;
    __syncthreads();
    const float padc = (float)(NCH * CH - M);
    if (tid < 64) {
        float s = 0.f;
        #pragma unroll
        for (int j = 0; j < 8; j++) s += red[tid * 8 + j];
        s -= padc;                           // remove exact pad contribution (fexp(0)==1)
        Zs[tid] = 1.0f / s;
        float T = logf(LAMBF * s) - 1e-3f;   // conservative skip threshold
        Ts[tid] = T;
        tenc[tid] = encf(T);
    }
    __syncthreads();
    // chunk flags
    if (tid < NCH) {
        int f = 0;
        #pragma unroll 4
        for (int r = 0; r < 64; r++) f |= (rmax[tid * 64 + r] > tenc[r]);
        flg[tid] = f;
    }
    __syncthreads();

    // ================= PHASE A (rare): flagged chunks =================
    const float invZ0 = Zs[r0l], invZ1 = Zs[r1l];
    const float T0 = Ts[r0l],    T1 = Ts[r1l];
    float s0 = 0.f, s1 = 0.f;
    float zac[64] = {};
    int any = 0;
    for (int ch = 0; ch < NCH; ch++) {
        if (!flg[ch]) continue;
        any = 1;
        copyB(sbase + B1A_OFF, g_mn + (size_t)ch * CH * DD);
        CPCOMMIT(); CPWAIT(0);
        __syncthreads();
        float acc[16] = {};
        gemm1(sA, sbase + B1A_OFF, wr, wc, lane, acc);
        float* w0 = wout + (gr0 + r0l) * (long long)M;
        float* w1 = wout + (gr0 + r1l) * (long long)M;
        #pragma unroll
        for (int nt = 0; nt < 4; nt++) {
            int cl  = wc * 32 + nt * 8 + 2 * (lane & 3);
            int col = ch * CH + cl;
            float h00 = 0.f, h01 = 0.f, h10 = 0.f, h11 = 0.f;
            if (col < M) {
                float a0 = acc[nt*4+0], a1 = acc[nt*4+1], a2 = acc[nt*4+2], a3 = acc[nt*4+3];
                if (a0 > T0) h00 = shrinkf(fexp(a0) * invZ0);
                if (a1 > T0) h01 = shrinkf(fexp(a1) * invZ0);
                if (a2 > T1) h10 = shrinkf(fexp(a2) * invZ1);
                if (a3 > T1) h11 = shrinkf(fexp(a3) * invZ1);
                s0 += h00 + h01; s1 += h10 + h11;
                *(float2*)(w0 + col) = make_float2(h00, h01);   // unnormalized; fixed up later
                *(float2*)(w1 + col) = make_float2(h10, h11);
            }
            *(uint32_t*)(smc + P_OFF + r0l * 128 + (((cl >> 3) ^ (r0l & 7)) << 4) + (cl & 7) * 2)
                = bf2(h00, h01);
            *(uint32_t*)(smc + P_OFF + r1l * 128 + (((cl >> 3) ^ (r1l & 7)) << 4) + (cl & 7) * 2)
                = bf2(h10, h11);
        }
        __syncthreads();
        copyB(sbase + B1B_OFF, g_mt + (size_t)ch * CH * DD);
        CPCOMMIT(); CPWAIT(0);
        __syncthreads();
        gemm2(sbase + P_OFF, sbase + B1B_OFF, wr, wc, lane, zac);
        __syncthreads();
    }

    // ---- S reduction ----
    red[r0l * 8 + wc * 4 + (lane & 3)] = s0;
    red[r1l * 8 + wc * 4 + (lane & 3)] = s1;
    __syncthreads();
    if (tid < 64) {
        float s = 0.f;
        #pragma unroll
        for (int j = 0; j < 8; j++) s += red[tid * 8 + j];
        Ss[tid] = 1.0f / (s + EPSS);
    }
    __syncthreads();

    // ---- fixup flagged chunks: w_hat *= invS ----
    if (any) {
        for (int ch = 0; ch < NCH; ch++) {
            if (!flg[ch]) continue;
            for (int idx = tid; idx < 64 * 16; idx += TPB) {
                int r = idx >> 4;
                int c4 = ch * CH + (idx & 15) * 4;
                if (c4 < M) {
                    float4* p = (float4*)(wout + (gr0 + r) * (long long)M + c4);
                    float4 v = *p; float s = Ss[r];
                    v.x *= s; v.y *= s; v.z *= s; v.w *= s;
                    *p = v;
                }
            }
        }
        __syncthreads();
    }

    // ---- z_hat epilogue ----
    {
        const float invS0 = Ss[r0l], invS1 = Ss[r1l];
        float* zr0 = zhat + (gr0 + r0l) * DD;
        float* zr1 = zhat + (gr0 + r1l) * DD;
        #pragma unroll
        for (int g = 0; g < 8; g++) {
            #pragma unroll
            for (int t = 0; t < 2; t++) {
                int d = wc * 128 + g * 16 + t * 8 + 2 * (lane & 3);
                int ii = (g * 2 + t) * 4;
                *(float2*)(zr0 + d) = make_float2(zac[ii + 0] * invS0, zac[ii + 1] * invS0);
                *(float2*)(zr1 + d) = make_float2(zac[ii + 2] * invS1, zac[ii + 3] * invS1);
            }
        }
    }
}

// ---------------- host ----------------
extern "C" void kernel_launch(void* const* d_in, const int* in_sizes, int n_in,
                              void* d_out, int out_size) {
    const float* z   = (const float*)d_in[0];
    const float* mem = (const float*)d_in[1];
    const int N = in_sizes[0] / DD;
    const int M = in_sizes[1] / DD;
    const int NCH = (M + CH - 1) / CH;

    float* zhat = (float*)d_out;                 // [N, 256]
    float* wout = zhat + (size_t)N * DD;         // [N, M]

    cudaFuncSetAttribute(mm_main, cudaFuncAttributeMaxDynamicSharedMemorySize, SM_TOT);

    mm_prep<<<NCH * CH, 256>>>(mem, M);
    mm_main<<<N / RB, TPB, SM_TOT>>>(z, wout, zhat, M, NCH);
}